// round 8
// baseline (speedup 1.0000x reference)
#include <cuda_runtime.h>
#include <cuda_fp16.h>
#include <cstdint>
#include <cstddef>

// LSTM: B == H == 1024, S = 128, I = 1024.
//   XP[b][s][col'] = x_s @ Wx + bias        (one parallel GEMM)
//   per step: gates = h @ Wh + XP[.,s,.]    (K=1024 fp16 GEMM, fused cell)
// fp16 single-product. Pipeline fills via cp.async.bulk (1 thread, mbarrier)
// from pre-tiled pre-swizzled global buffers. col' = 4n+g (i,f,g,o).

#define HID  1024
#define SLEN 128
#define NGC  4096
#define KH   1024
#define NSLAB (KH / 32)      // 32

#define BM 128
#define BN 256
#define BK 32

#define A_TILE_B 8192        // 128 x 32 fp16
#define B_TILE_B 16384       // 256 x 32 fp16
#define STAGE_B  (A_TILE_B + B_TILE_B)     // 24576
#define GS 260
#define GSM_B (128 * GS * 4)               // 133120
#define HSTG_B 16384
#define SMEM_B (GSM_B + HSTG_B)            // 149504

// per-tile half counts
#define A_TILE_H 4096
#define B_TILE_H 8192
#define MT_H (32 * A_TILE_H)   // halfs per A m-tile (all 32 slabs) = 131072
#define NT_H (32 * B_TILE_H)   // halfs per B n-tile = 262144

// ---- static device scratch (each < 2GB) ----
__device__ __align__(1024) __half g_WhT[(size_t)16 * NT_H];        // 8 MB tiled
__device__ __align__(1024) __half g_WxT[(size_t)16 * NT_H];        // 8 MB tiled
__device__ __align__(1024) __half g_XT[(size_t)HID * MT_H];        // 256 MB tiled
__device__ __align__(1024) __half g_HaT[2][(size_t)8 * MT_H];      // 2 MB each, tiled
__device__ float g_bias[NGC];
__device__ float g_XP0[(size_t)HID * 64 * NGC];                    // 1 GB
__device__ float g_XP1[(size_t)HID * 64 * NGC];                    // 1 GB

// ---- helpers ----
__device__ __forceinline__ uint32_t smem_u32(const void* p) {
    uint32_t a;
    asm("{ .reg .u64 t; cvta.to.shared.u64 t, %1; cvt.u32.u64 %0, t; }" : "=r"(a) : "l"(p));
    return a;
}
__device__ __forceinline__ void mbar_init(uint32_t bar, uint32_t cnt) {
    asm volatile("mbarrier.init.shared.b64 [%0], %1;" :: "r"(bar), "r"(cnt) : "memory");
}
__device__ __forceinline__ void mbar_wait(uint32_t bar, uint32_t parity) {
    asm volatile(
        "{\n\t.reg .pred P;\n\tWL_%=:\n\t"
        "mbarrier.try_wait.parity.acquire.cta.shared::cta.b64 P, [%0], %1, 0x989680;\n\t"
        "@P bra.uni WD_%=;\n\tbra.uni WL_%=;\n\tWD_%=:\n\t}"
        :: "r"(bar), "r"(parity) : "memory");
}
__device__ __forceinline__ void expect_tx(uint32_t bar, uint32_t bytes) {
    asm volatile("mbarrier.arrive.expect_tx.shared.b64 _, [%0], %1;"
                 :: "r"(bar), "r"(bytes) : "memory");
}
__device__ __forceinline__ void bulk_ld(uint32_t dst, const void* src,
                                        uint32_t bytes, uint32_t bar) {
    asm volatile(
        "cp.async.bulk.shared::cluster.global.mbarrier::complete_tx::bytes "
        "[%0], [%1], %2, [%3];"
        :: "r"(dst), "l"(src), "r"(bytes), "r"(bar) : "memory");
}
__device__ __forceinline__ void bulk_st(void* dst, uint32_t src, uint32_t bytes) {
    asm volatile("cp.async.bulk.global.shared::cta.bulk_group [%0], [%1], %2;"
        :: "l"(dst), "r"(src), "r"(bytes) : "memory");
}
__device__ __forceinline__ void ldm_x4(uint32_t* r, uint32_t addr) {
    asm volatile("ldmatrix.sync.aligned.m8n8.x4.shared.b16 {%0,%1,%2,%3}, [%4];"
        : "=r"(r[0]), "=r"(r[1]), "=r"(r[2]), "=r"(r[3]) : "r"(addr));
}
__device__ __forceinline__ void mma16816(float* c, const uint32_t* a, const uint32_t* b) {
    asm volatile(
        "mma.sync.aligned.m16n8k16.row.col.f32.f16.f16.f32 "
        "{%0,%1,%2,%3}, {%4,%5,%6,%7}, {%8,%9}, {%0,%1,%2,%3};\n"
        : "+f"(c[0]), "+f"(c[1]), "+f"(c[2]), "+f"(c[3])
        : "r"(a[0]), "r"(a[1]), "r"(a[2]), "r"(a[3]), "r"(b[0]), "r"(b[1]));
}
__device__ __forceinline__ uint32_t swq(int row, int q) {
    return (uint32_t)(row * 64 + ((q ^ ((row >> 1) & 3)) << 4));
}
__device__ __forceinline__ float sigm(float x) { return 1.0f / (1.0f + __expf(-x)); }
__device__ __forceinline__ float tanh_f(float x) { return 1.0f - 2.0f / (__expf(2.0f * x) + 1.0f); }

__device__ __forceinline__ void slab_mma(
    uint32_t stb, int wm, int wn, int lane, float acc[2][8][4])
{
    #pragma unroll
    for (int kk = 0; kk < 2; ++kk) {
        uint32_t ra[2][4];
        #pragma unroll
        for (int mt = 0; mt < 2; ++mt) {
            const int row = wm * 32 + mt * 16 + (lane & 15);
            const int q   = kk * 2 + (lane >> 4);
            ldm_x4(ra[mt], stb + swq(row, q));
        }
        #pragma unroll
        for (int p = 0; p < 4; ++p) {
            const int row = wn * 64 + p * 16 + (lane & 7) + ((lane >> 4) << 3);
            const int q   = kk * 2 + ((lane >> 3) & 1);
            uint32_t rb[4];
            ldm_x4(rb, stb + A_TILE_B + swq(row, q));
            #pragma unroll
            for (int mt = 0; mt < 2; ++mt) {
                mma16816(acc[mt][2 * p],     ra[mt], rb);
                mma16816(acc[mt][2 * p + 1], ra[mt], rb + 2);
            }
        }
    }
}

__device__ __forceinline__ void stage_gates(
    float* gsm, int wm, int wn, int lane, float acc[2][8][4])
{
    #pragma unroll
    for (int mt = 0; mt < 2; ++mt) {
        const int row = wm * 32 + mt * 16 + (lane >> 2);
        #pragma unroll
        for (int nt = 0; nt < 8; ++nt) {
            const int c0 = wn * 64 + nt * 8 + 2 * (lane & 3);
            *reinterpret_cast<float2*>(&gsm[row * GS + c0]) =
                make_float2(acc[mt][nt][0], acc[mt][nt][1]);
            *reinterpret_cast<float2*>(&gsm[(row + 8) * GS + c0]) =
                make_float2(acc[mt][nt][2], acc[mt][nt][3]);
        }
    }
}

// Bulk-fed mainloop: A tiles aT + kt*A_TILE_H, B tiles bT + kt*B_TILE_H
__device__ __forceinline__ void gemm_mainloop(
    uint32_t sbase, uint32_t bar0, const __half* aT, const __half* bT,
    int tid, int wm, int wn, int lane, float acc[2][8][4])
{
    if (tid == 0) {
        #pragma unroll
        for (int i = 0; i < 3; ++i) {
            expect_tx(bar0 + i * 8, STAGE_B);
            bulk_ld(sbase + i * STAGE_B,            aT + i * A_TILE_H, A_TILE_B, bar0 + i * 8);
            bulk_ld(sbase + i * STAGE_B + A_TILE_B, bT + i * B_TILE_H, B_TILE_B, bar0 + i * 8);
        }
    }
    for (int kt = 0; kt < NSLAB; ++kt) {
        const int st = kt & 3;
        mbar_wait(bar0 + st * 8, (kt >> 2) & 1);
        slab_mma(sbase + st * STAGE_B, wm, wn, lane, acc);
        __syncthreads();
        if (tid == 0 && kt + 3 < NSLAB) {
            const int k2 = kt + 3, s2 = k2 & 3;
            expect_tx(bar0 + s2 * 8, STAGE_B);
            bulk_ld(sbase + s2 * STAGE_B,            aT + k2 * A_TILE_H, A_TILE_B, bar0 + s2 * 8);
            bulk_ld(sbase + s2 * STAGE_B + A_TILE_B, bT + k2 * B_TILE_H, B_TILE_B, bar0 + s2 * 8);
        }
    }
}

// ---------------------------------------------------------------------------
// Prep kernels (write tiled, pre-swizzled layouts)
// ---------------------------------------------------------------------------
__global__ void prep_weights(
    const float* __restrict__ w_ii, const float* __restrict__ w_hi,
    const float* __restrict__ w_if, const float* __restrict__ w_hf,
    const float* __restrict__ w_ig, const float* __restrict__ w_hg,
    const float* __restrict__ w_io, const float* __restrict__ w_ho)
{
    // one 16B chunk (8 k-values) per thread; total 4096 cols * 128 chunks
    int idx = blockIdx.x * blockDim.x + threadIdx.x;
    if (idx >= NGC * 128) return;
    const int colp = idx >> 7;           // col' = 4n+g
    const int c8   = idx & 127;          // chunk: k0 = c8*8
    const int n    = colp >> 2;
    const int g    = colp & 3;
    const int slab = c8 >> 2, qc = c8 & 3;
    const int k0   = c8 * 8;
    const int nt   = colp >> 8, trow = colp & 255;
    const size_t byteoff = (size_t)nt * (NT_H * 2) + (size_t)slab * B_TILE_B
                         + trow * 64 + (((uint32_t)(qc ^ ((trow >> 1) & 3))) << 4);
    const float* wh = (g == 0) ? w_hi : (g == 1) ? w_hf : (g == 2) ? w_hg : w_ho;
    const float* wx = (g == 0) ? w_ii : (g == 1) ? w_if : (g == 2) ? w_ig : w_io;
    __half vh[8], vx[8];
    #pragma unroll
    for (int j = 0; j < 8; ++j) {
        vh[j] = __float2half_rn(wh[(size_t)(k0 + j) * HID + n]);
        vx[j] = __float2half_rn(wx[(size_t)(k0 + j) * HID + n]);
    }
    *reinterpret_cast<uint4*>(reinterpret_cast<char*>(g_WhT) + byteoff) =
        *reinterpret_cast<const uint4*>(vh);
    *reinterpret_cast<uint4*>(reinterpret_cast<char*>(g_WxT) + byteoff) =
        *reinterpret_cast<const uint4*>(vx);
}

__global__ void prep_x(const float* __restrict__ x)
{
    // one 16B chunk per thread; total 1024*128*128 chunks
    size_t idx = (size_t)blockIdx.x * blockDim.x + threadIdx.x;
    if (idx >= (size_t)HID * SLEN * 128) return;
    const int b   = (int)(idx >> 14);
    const int rem = (int)(idx & 16383);
    const int s   = rem >> 7;
    const int c8  = rem & 127;
    const int slab = c8 >> 2, qc = c8 & 3;
    const float* src = x + ((size_t)b * SLEN + s) * HID + c8 * 8;
    __half v[8];
    #pragma unroll
    for (int j = 0; j < 8; ++j) v[j] = __float2half_rn(src[j]);
    const size_t byteoff = (size_t)b * (MT_H * 2) + (size_t)slab * A_TILE_B
                         + s * 64 + (((uint32_t)(qc ^ ((s >> 1) & 3))) << 4);
    *reinterpret_cast<uint4*>(reinterpret_cast<char*>(g_XT) + byteoff) =
        *reinterpret_cast<const uint4*>(v);
}

__global__ void prep_state(
    const float* __restrict__ b_ii, const float* __restrict__ b_hi,
    const float* __restrict__ b_if, const float* __restrict__ b_hf,
    const float* __restrict__ b_ig, const float* __restrict__ b_hg,
    const float* __restrict__ b_io, const float* __restrict__ b_ho,
    float* __restrict__ c)
{
    int idx = blockIdx.x * blockDim.x + threadIdx.x;
    if (idx < HID * HID) {
        c[idx] = 0.0f;
        reinterpret_cast<uint32_t*>(g_HaT[0])[idx >> 1 << 1 >> 1] = 0u;  // see below
    }
    // zero h tile buffer 0 cleanly (2M halfs = 1M words)
    if (idx < (int)(8 * MT_H / 2))
        reinterpret_cast<uint32_t*>(g_HaT[0])[idx] = 0u;
    if (idx < NGC) {
        int n = idx >> 2, g = idx & 3;
        const float* bi = (g == 0) ? b_ii : (g == 1) ? b_if : (g == 2) ? b_ig : b_io;
        const float* bh = (g == 0) ? b_hi : (g == 1) ? b_hf : (g == 2) ? b_hg : b_ho;
        g_bias[idx] = bi[n] + bh[n];
    }
}

// ---------------------------------------------------------------------------
// xproj: XP = x @ Wx + bias (M = 131072 rows = [b][s])
// ---------------------------------------------------------------------------
__global__ __launch_bounds__(512, 1) void xproj_gemm()
{
    extern __shared__ __align__(128) char smem[];
    __shared__ __align__(8) uint64_t barr[4];
    __shared__ __align__(16) float sbias[BN];

    const int tid  = threadIdx.x;
    const int lane = tid & 31;
    const int warp = tid >> 5;
    const int wm   = warp >> 2;
    const int wn   = warp & 3;
    const int bn   = blockIdx.x * BN;
    const int bt   = blockIdx.y;           // b tile (= batch index)
    const uint32_t sbase = smem_u32(smem);
    const uint32_t bar0  = smem_u32(barr);

    if (tid == 0) {
        #pragma unroll
        for (int i = 0; i < 4; ++i) mbar_init(bar0 + i * 8, 1);
        asm volatile("fence.proxy.async.shared::cta;" ::: "memory");
    }
    if (tid < BN) sbias[tid] = g_bias[bn + tid];
    __syncthreads();

    float acc[2][8][4];
    #pragma unroll
    for (int a = 0; a < 2; ++a)
        #pragma unroll
        for (int b = 0; b < 8; ++b)
            #pragma unroll
            for (int v = 0; v < 4; ++v) acc[a][b][v] = 0.0f;

    gemm_mainloop(sbase, bar0,
                  g_XT + (size_t)bt * MT_H,
                  g_WxT + (size_t)(bn / BN) * NT_H,
                  tid, wm, wn, lane, acc);

    float* gsm = (float*)smem;
    stage_gates(gsm, wm, wn, lane, acc);
    __syncthreads();

    #pragma unroll 4
    for (int it = 0; it < 16; ++it) {
        const int row = it * 8 + (tid >> 6);   // = s
        const int n   = tid & 63;
        float4 gv = *reinterpret_cast<const float4*>(&gsm[row * GS + 4 * n]);
        const float4 bv = *reinterpret_cast<const float4*>(&sbias[4 * n]);
        gv.x += bv.x; gv.y += bv.y; gv.z += bv.z; gv.w += bv.w;
        float* dst = (row < 64 ? g_XP0 : g_XP1)
                   + ((size_t)bt * 64 + (row & 63)) * NGC + bn + 4 * n;
        *reinterpret_cast<float4*>(dst) = gv;
    }
}

// ---------------------------------------------------------------------------
// Per-step: gates = h @ Wh + XP[.,s,.]; fused cell; h written as bulk tile.
// ---------------------------------------------------------------------------
__global__ __launch_bounds__(512, 1) void lstm_step(
    int s, float* __restrict__ h_g, float* __restrict__ c_g)
{
    extern __shared__ __align__(128) char smem[];
    __shared__ __align__(8) uint64_t barr[4];

    const int tid  = threadIdx.x;
    const int lane = tid & 31;
    const int warp = tid >> 5;
    const int wm   = warp >> 2;
    const int wn   = warp & 3;
    const int bm   = blockIdx.y * BM;
    const int bn   = blockIdx.x * BN;
    const int rdbuf = s & 1;
    const int wrbuf = rdbuf ^ 1;
    const uint32_t sbase = smem_u32(smem);
    const uint32_t bar0  = smem_u32(barr);

    if (tid == 0) {
        #pragma unroll
        for (int i = 0; i < 4; ++i) mbar_init(bar0 + i * 8, 1);
        asm volatile("fence.proxy.async.shared::cta;" ::: "memory");
    }
    __syncthreads();

    float acc[2][8][4];
    #pragma unroll
    for (int a = 0; a < 2; ++a)
        #pragma unroll
        for (int b = 0; b < 8; ++b)
            #pragma unroll
            for (int v = 0; v < 4; ++v) acc[a][b][v] = 0.0f;

    gemm_mainloop(sbase, bar0,
                  g_HaT[rdbuf] + (size_t)blockIdx.y * MT_H,
                  g_WhT + (size_t)(bn / BN) * NT_H,
                  tid, wm, wn, lane, acc);

    float* gsm = (float*)smem;
    stage_gates(gsm, wm, wn, lane, acc);
    __syncthreads();

    // ---- fused cell update; stage new h tile (fp16, swizzled) in smem ----
    char* hstg = smem + GSM_B;                 // 16KB: [2 slabs][128 rows][64B]
    const int n0g = bn >> 2;
    const float* xp = (s < 64 ? g_XP0 : g_XP1);
    const int ss = s & 63;
    const bool last = (s == SLEN - 1);
    #pragma unroll 4
    for (int it = 0; it < 16; ++it) {
        const int row = it * 8 + (tid >> 6);
        const int n   = tid & 63;
        const float4 gv = *reinterpret_cast<const float4*>(&gsm[row * GS + 4 * n]);
        const float4 xv = *reinterpret_cast<const float4*>(
            &xp[((size_t)(bm + row) * 64 + ss) * NGC + bn + 4 * n]);
        const float ig = sigm(gv.x + xv.x);
        const float fg = sigm(gv.y + xv.y);
        const float gg = tanh_f(gv.z + xv.z);
        const float og = sigm(gv.w + xv.w);
        const size_t gi = (size_t)(bm + row) * HID + n0g + n;
        const float cc = fg * c_g[gi] + ig * gg;
        c_g[gi] = cc;
        const float hh = og * tanh_f(cc);
        if (last) h_g[gi] = hh;
        const int slab = n >> 5, col = n & 31;
        *reinterpret_cast<__half*>(hstg + slab * A_TILE_B + row * 64
            + (((col >> 3) ^ ((row >> 1) & 3)) << 4) + (col & 7) * 2)
            = __float2half_rn(hh);
    }
    __syncthreads();
    if (tid == 0) {
        asm volatile("fence.proxy.async.shared::cta;" ::: "memory");
        bulk_st(g_HaT[wrbuf] + (size_t)blockIdx.y * MT_H + (size_t)(n0g >> 5) * A_TILE_H,
                smem_u32(hstg), HSTG_B);
        asm volatile("cp.async.bulk.commit_group;" ::: "memory");
        asm volatile("cp.async.bulk.wait_group 0;" ::: "memory");
    }
    __syncthreads();
}

// ---------------------------------------------------------------------------
extern "C" void kernel_launch(void* const* d_in, const int* in_sizes, int n_in,
                              void* d_out, int out_size)
{
    const float* x = nullptr;
    const float* w[8] = {nullptr};
    const float* b[8] = {nullptr};
    int wi = 0, bi = 0;
    for (int i = 0; i < n_in; ++i) {
        const int sz = in_sizes[i];
        if (sz == HID * HID)      { if (wi < 8) w[wi++] = (const float*)d_in[i]; }
        else if (sz == HID)       { if (bi < 8) b[bi++] = (const float*)d_in[i]; }
        else                      { x = (const float*)d_in[i]; }
    }

    float* h = (float*)d_out;
    float* c = h + (size_t)HID * HID;

    cudaFuncSetAttribute(xproj_gemm, cudaFuncAttributeMaxDynamicSharedMemorySize, SMEM_B);
    cudaFuncSetAttribute(lstm_step,  cudaFuncAttributeMaxDynamicSharedMemorySize, SMEM_B);

    prep_weights<<<(NGC * 128 + 255) / 256, 256>>>(
        w[0], w[1], w[2], w[3], w[4], w[5], w[6], w[7]);
    {
        const size_t total = (size_t)HID * SLEN * 128;
        prep_x<<<(unsigned)((total + 255) / 256), 256>>>(x);
    }
    prep_state<<<(HID * HID) / 256, 256>>>(
        b[0], b[1], b[2], b[3], b[4], b[5], b[6], b[7], c);

    {
        dim3 grid(NGC / BN, HID);                 // 16 x 1024
        xproj_gemm<<<grid, 512, SMEM_B>>>();
    }
    dim3 grid(NGC / BN, HID / BM);                // 16 x 8 = 128 CTAs
    for (int s = 0; s < SLEN; ++s)
        lstm_step<<<grid, 512, SMEM_B>>>(s, h, c);
}

// round 9
// speedup vs baseline: 1.1966x; 1.1966x over previous
#include <cuda_runtime.h>
#include <cuda_fp16.h>
#include <cstdint>
#include <cstddef>

// LSTM: B == H == 1024, S = 128, I = 1024.
//   XP[b][s][col'] = x_s @ Wx + bias        (one parallel GEMM)
//   per step: gates = h @ Wh + XP[.,s,.]    (K=1024 fp16 GEMM, fused cell)
// fp16 single-product. 4-stage mbarrier ring (full tx-barriers + empty
// arrive-barriers), NO per-slab __syncthreads. BK=64, SW128 swizzle.

#define HID  1024
#define SLEN 128
#define NGC  4096
#define KH   1024

#define BM 128
#define BN 256
#define BK 64
#define NSLAB  (KH / BK)     // 16
#define NSTAGE 4

#define A_TILE_B 16384       // 128 x 64 fp16
#define B_TILE_B 32768       // 256 x 64 fp16
#define STAGE_B  (A_TILE_B + B_TILE_B)   // 49152
#define SMEM_B   (NSTAGE * STAGE_B)      // 196608
#define GS 260
#define GSM_B (128 * GS * 4)             // 133120 (overlays ring after loop)
#define HSTG_OFF GSM_B                   // h staging tile, 16 KB

#define A_TILE_H 8192        // halfs per A slab tile
#define B_TILE_H 16384       // halfs per B slab tile
#define MT_H (NSLAB * A_TILE_H)   // 131072 halfs per A m-tile
#define NT_H (NSLAB * B_TILE_H)   // 262144 halfs per B n-tile

// ---- static device scratch (each < 2GB) ----
__device__ __align__(1024) __half g_WhT[(size_t)16 * NT_H];
__device__ __align__(1024) __half g_WxT[(size_t)16 * NT_H];
__device__ __align__(1024) __half g_XT[(size_t)HID * MT_H];
__device__ __align__(1024) __half g_HaT[2][(size_t)8 * MT_H];
__device__ float g_bias[NGC];
__device__ float g_XP0[(size_t)HID * 64 * NGC];
__device__ float g_XP1[(size_t)HID * 64 * NGC];

// ---- helpers ----
__device__ __forceinline__ uint32_t smem_u32(const void* p) {
    uint32_t a;
    asm("{ .reg .u64 t; cvta.to.shared.u64 t, %1; cvt.u32.u64 %0, t; }" : "=r"(a) : "l"(p));
    return a;
}
__device__ __forceinline__ void mbar_init(uint32_t bar, uint32_t cnt) {
    asm volatile("mbarrier.init.shared.b64 [%0], %1;" :: "r"(bar), "r"(cnt) : "memory");
}
__device__ __forceinline__ void mbar_arrive(uint32_t bar) {
    asm volatile("mbarrier.arrive.shared.b64 _, [%0];" :: "r"(bar) : "memory");
}
__device__ __forceinline__ void mbar_wait(uint32_t bar, uint32_t parity) {
    asm volatile(
        "{\n\t.reg .pred P;\n\tWL_%=:\n\t"
        "mbarrier.try_wait.parity.acquire.cta.shared::cta.b64 P, [%0], %1, 0x989680;\n\t"
        "@P bra.uni WD_%=;\n\tbra.uni WL_%=;\n\tWD_%=:\n\t}"
        :: "r"(bar), "r"(parity) : "memory");
}
__device__ __forceinline__ void expect_tx(uint32_t bar, uint32_t bytes) {
    asm volatile("mbarrier.arrive.expect_tx.shared.b64 _, [%0], %1;"
                 :: "r"(bar), "r"(bytes) : "memory");
}
__device__ __forceinline__ void bulk_ld(uint32_t dst, const void* src,
                                        uint32_t bytes, uint32_t bar) {
    asm volatile(
        "cp.async.bulk.shared::cluster.global.mbarrier::complete_tx::bytes "
        "[%0], [%1], %2, [%3];"
        :: "r"(dst), "l"(src), "r"(bytes), "r"(bar) : "memory");
}
__device__ __forceinline__ void bulk_st(void* dst, uint32_t src, uint32_t bytes) {
    asm volatile("cp.async.bulk.global.shared::cta.bulk_group [%0], [%1], %2;"
        :: "l"(dst), "r"(src), "r"(bytes) : "memory");
}
__device__ __forceinline__ void ldm_x4(uint32_t* r, uint32_t addr) {
    asm volatile("ldmatrix.sync.aligned.m8n8.x4.shared.b16 {%0,%1,%2,%3}, [%4];"
        : "=r"(r[0]), "=r"(r[1]), "=r"(r[2]), "=r"(r[3]) : "r"(addr));
}
__device__ __forceinline__ void mma16816(float* c, const uint32_t* a, const uint32_t* b) {
    asm volatile(
        "mma.sync.aligned.m16n8k16.row.col.f32.f16.f16.f32 "
        "{%0,%1,%2,%3}, {%4,%5,%6,%7}, {%8,%9}, {%0,%1,%2,%3};\n"
        : "+f"(c[0]), "+f"(c[1]), "+f"(c[2]), "+f"(c[3])
        : "r"(a[0]), "r"(a[1]), "r"(a[2]), "r"(a[3]), "r"(b[0]), "r"(b[1]));
}
// SW128 swizzle for 128B rows: 16B chunk q (0..7) -> q ^ (row & 7)
__device__ __forceinline__ uint32_t sw(int row, int q) {
    return (uint32_t)(row * 128 + ((q ^ (row & 7)) << 4));
}
__device__ __forceinline__ float sigm(float x) { return 1.0f / (1.0f + __expf(-x)); }
__device__ __forceinline__ float tanh_f(float x) { return 1.0f - 2.0f / (__expf(2.0f * x) + 1.0f); }

// One BK=64 slab of MMAs for this warp
__device__ __forceinline__ void slab_mma(
    uint32_t stb, int wm, int wn, int lane, float acc[2][8][4])
{
    #pragma unroll
    for (int kk = 0; kk < 4; ++kk) {              // four k16 chunks
        uint32_t ra[2][4];
        #pragma unroll
        for (int mt = 0; mt < 2; ++mt) {
            const int row = wm * 32 + mt * 16 + (lane & 15);
            const int q   = kk * 2 + (lane >> 4);
            ldm_x4(ra[mt], stb + sw(row, q));
        }
        #pragma unroll
        for (int p = 0; p < 4; ++p) {
            const int row = wn * 64 + p * 16 + (lane & 7) + ((lane >> 4) << 3);
            const int q   = kk * 2 + ((lane >> 3) & 1);
            uint32_t rb[4];
            ldm_x4(rb, stb + A_TILE_B + sw(row, q));
            #pragma unroll
            for (int mt = 0; mt < 2; ++mt) {
                mma16816(acc[mt][2 * p],     ra[mt], rb);
                mma16816(acc[mt][2 * p + 1], ra[mt], rb + 2);
            }
        }
    }
}

__device__ __forceinline__ void stage_gates(
    float* gsm, int wm, int wn, int lane, float acc[2][8][4])
{
    #pragma unroll
    for (int mt = 0; mt < 2; ++mt) {
        const int row = wm * 32 + mt * 16 + (lane >> 2);
        #pragma unroll
        for (int nt = 0; nt < 8; ++nt) {
            const int c0 = wn * 64 + nt * 8 + 2 * (lane & 3);
            *reinterpret_cast<float2*>(&gsm[row * GS + c0]) =
                make_float2(acc[mt][nt][0], acc[mt][nt][1]);
            *reinterpret_cast<float2*>(&gsm[(row + 8) * GS + c0]) =
                make_float2(acc[mt][nt][2], acc[mt][nt][3]);
        }
    }
}

// Mainloop: full/empty mbarrier ring, no __syncthreads.
// fullb[i] = fb0 + i*8 (count 1, tx); emptyb[i] = fb0 + 32 + i*8 (count 16).
__device__ __forceinline__ void gemm_mainloop(
    uint32_t sbase, uint32_t fb0, const __half* aT, const __half* bT,
    int tid, int lane, int wm, int wn, float acc[2][8][4])
{
    if (tid == 0) {
        #pragma unroll
        for (int i = 0; i < NSTAGE; ++i) {
            expect_tx(fb0 + i * 8, STAGE_B);
            bulk_ld(sbase + i * STAGE_B,            aT + i * A_TILE_H, A_TILE_B, fb0 + i * 8);
            bulk_ld(sbase + i * STAGE_B + A_TILE_B, bT + i * B_TILE_H, B_TILE_B, fb0 + i * 8);
        }
    }
    for (int kt = 0; kt < NSLAB; ++kt) {
        const int st = kt & 3;
        const int m  = kt >> 2;
        mbar_wait(fb0 + st * 8, m & 1);
        slab_mma(sbase + st * STAGE_B, wm, wn, lane, acc);
        if (lane == 0) mbar_arrive(fb0 + 32 + st * 8);
        if (tid == 0 && kt + NSTAGE < NSLAB) {
            mbar_wait(fb0 + 32 + st * 8, m & 1);   // all 16 warps done with slab kt
            const int k2 = kt + NSTAGE;
            expect_tx(fb0 + st * 8, STAGE_B);
            bulk_ld(sbase + st * STAGE_B,            aT + k2 * A_TILE_H, A_TILE_B, fb0 + st * 8);
            bulk_ld(sbase + st * STAGE_B + A_TILE_B, bT + k2 * B_TILE_H, B_TILE_B, fb0 + st * 8);
        }
    }
}

// ---------------------------------------------------------------------------
// Prep kernels (tiled, pre-swizzled layouts; 128B rows)
// ---------------------------------------------------------------------------
__global__ void prep_weights(
    const float* __restrict__ w_ii, const float* __restrict__ w_hi,
    const float* __restrict__ w_if, const float* __restrict__ w_hf,
    const float* __restrict__ w_ig, const float* __restrict__ w_hg,
    const float* __restrict__ w_io, const float* __restrict__ w_ho)
{
    int idx = blockIdx.x * blockDim.x + threadIdx.x;
    if (idx >= NGC * 128) return;
    const int colp = idx >> 7;           // col' = 4n+g
    const int c8   = idx & 127;          // 16B chunk; k0 = c8*8
    const int n    = colp >> 2;
    const int g    = colp & 3;
    const int slab = c8 >> 3, q = c8 & 7;
    const int k0   = c8 * 8;
    const int nt   = colp >> 8, trow = colp & 255;
    const size_t byteoff = (size_t)nt * (NT_H * 2) + (size_t)slab * B_TILE_B + sw(trow, q);
    const float* wh = (g == 0) ? w_hi : (g == 1) ? w_hf : (g == 2) ? w_hg : w_ho;
    const float* wx = (g == 0) ? w_ii : (g == 1) ? w_if : (g == 2) ? w_ig : w_io;
    __half vh[8], vx[8];
    #pragma unroll
    for (int j = 0; j < 8; ++j) {
        vh[j] = __float2half_rn(wh[(size_t)(k0 + j) * HID + n]);
        vx[j] = __float2half_rn(wx[(size_t)(k0 + j) * HID + n]);
    }
    *reinterpret_cast<uint4*>(reinterpret_cast<char*>(g_WhT) + byteoff) =
        *reinterpret_cast<const uint4*>(vh);
    *reinterpret_cast<uint4*>(reinterpret_cast<char*>(g_WxT) + byteoff) =
        *reinterpret_cast<const uint4*>(vx);
}

__global__ void prep_x(const float* __restrict__ x)
{
    size_t idx = (size_t)blockIdx.x * blockDim.x + threadIdx.x;
    if (idx >= (size_t)HID * SLEN * 128) return;
    const int b   = (int)(idx >> 14);
    const int s   = (int)((idx >> 7) & 127);
    const int c8  = (int)(idx & 127);
    const int slab = c8 >> 3, q = c8 & 7;
    const float* src = x + ((size_t)b * SLEN + s) * HID + c8 * 8;
    __half v[8];
    #pragma unroll
    for (int j = 0; j < 8; ++j) v[j] = __float2half_rn(src[j]);
    const size_t byteoff = (size_t)b * (MT_H * 2) + (size_t)slab * A_TILE_B + sw(s, q);
    *reinterpret_cast<uint4*>(reinterpret_cast<char*>(g_XT) + byteoff) =
        *reinterpret_cast<const uint4*>(v);
}

__global__ void prep_state(
    const float* __restrict__ b_ii, const float* __restrict__ b_hi,
    const float* __restrict__ b_if, const float* __restrict__ b_hf,
    const float* __restrict__ b_ig, const float* __restrict__ b_hg,
    const float* __restrict__ b_io, const float* __restrict__ b_ho,
    float* __restrict__ c)
{
    int idx = blockIdx.x * blockDim.x + threadIdx.x;
    if (idx < HID * HID) c[idx] = 0.0f;
    if (idx < (int)(8 * MT_H / 2))
        reinterpret_cast<uint32_t*>(g_HaT[0])[idx] = 0u;
    if (idx < NGC) {
        int n = idx >> 2, g = idx & 3;
        const float* bi = (g == 0) ? b_ii : (g == 1) ? b_if : (g == 2) ? b_ig : b_io;
        const float* bh = (g == 0) ? b_hi : (g == 1) ? b_hf : (g == 2) ? b_hg : b_ho;
        g_bias[idx] = bi[n] + bh[n];
    }
}

// ---------------------------------------------------------------------------
// xproj: XP = x @ Wx + bias (M = [b][s] = 131072 rows)
// ---------------------------------------------------------------------------
__global__ __launch_bounds__(512, 1) void xproj_gemm()
{
    extern __shared__ __align__(128) char smem[];
    __shared__ __align__(8) uint64_t barr[8];
    __shared__ __align__(16) float sbias[BN];

    const int tid  = threadIdx.x;
    const int lane = tid & 31;
    const int warp = tid >> 5;
    const int wm   = warp >> 2;
    const int wn   = warp & 3;
    const int bn   = blockIdx.x * BN;
    const int bt   = blockIdx.y;
    const uint32_t sbase = smem_u32(smem);
    const uint32_t fb0   = smem_u32(barr);

    if (tid == 0) {
        #pragma unroll
        for (int i = 0; i < NSTAGE; ++i) {
            mbar_init(fb0 + i * 8, 1);        // full (tx)
            mbar_init(fb0 + 32 + i * 8, 16);  // empty (16 warps)
        }
        asm volatile("fence.proxy.async.shared::cta;" ::: "memory");
    }
    if (tid < BN) sbias[tid] = g_bias[bn + tid];
    __syncthreads();

    float acc[2][8][4];
    #pragma unroll
    for (int a = 0; a < 2; ++a)
        #pragma unroll
        for (int b = 0; b < 8; ++b)
            #pragma unroll
            for (int v = 0; v < 4; ++v) acc[a][b][v] = 0.0f;

    gemm_mainloop(sbase, fb0,
                  g_XT + (size_t)bt * MT_H,
                  g_WxT + (size_t)blockIdx.x * NT_H,
                  tid, lane, wm, wn, acc);
    __syncthreads();       // all warps done consuming; ring smem reusable

    float* gsm = (float*)smem;
    stage_gates(gsm, wm, wn, lane, acc);
    __syncthreads();

    #pragma unroll 4
    for (int it = 0; it < 16; ++it) {
        const int row = it * 8 + (tid >> 6);   // = s
        const int n   = tid & 63;
        float4 gv = *reinterpret_cast<const float4*>(&gsm[row * GS + 4 * n]);
        const float4 bv = *reinterpret_cast<const float4*>(&sbias[4 * n]);
        gv.x += bv.x; gv.y += bv.y; gv.z += bv.z; gv.w += bv.w;
        float* dst = (row < 64 ? g_XP0 : g_XP1)
                   + ((size_t)bt * 64 + (row & 63)) * NGC + bn + 4 * n;
        *reinterpret_cast<float4*>(dst) = gv;
    }
}

// ---------------------------------------------------------------------------
// Per-step: gates = h @ Wh + XP[.,s,.]; fused cell; h tile written via bulk.
// ---------------------------------------------------------------------------
__global__ __launch_bounds__(512, 1) void lstm_step(
    int s, float* __restrict__ h_g, float* __restrict__ c_g)
{
    extern __shared__ __align__(128) char smem[];
    __shared__ __align__(8) uint64_t barr[8];

    const int tid  = threadIdx.x;
    const int lane = tid & 31;
    const int warp = tid >> 5;
    const int wm   = warp >> 2;
    const int wn   = warp & 3;
    const int bm   = blockIdx.y * BM;
    const int bn   = blockIdx.x * BN;
    const int rdbuf = s & 1;
    const int wrbuf = rdbuf ^ 1;
    const uint32_t sbase = smem_u32(smem);
    const uint32_t fb0   = smem_u32(barr);

    if (tid == 0) {
        #pragma unroll
        for (int i = 0; i < NSTAGE; ++i) {
            mbar_init(fb0 + i * 8, 1);
            mbar_init(fb0 + 32 + i * 8, 16);
        }
        asm volatile("fence.proxy.async.shared::cta;" ::: "memory");
    }
    __syncthreads();

    float acc[2][8][4];
    #pragma unroll
    for (int a = 0; a < 2; ++a)
        #pragma unroll
        for (int b = 0; b < 8; ++b)
            #pragma unroll
            for (int v = 0; v < 4; ++v) acc[a][b][v] = 0.0f;

    gemm_mainloop(sbase, fb0,
                  g_HaT[rdbuf] + (size_t)blockIdx.y * MT_H,
                  g_WhT + (size_t)blockIdx.x * NT_H,
                  tid, lane, wm, wn, acc);
    __syncthreads();

    float* gsm = (float*)smem;
    stage_gates(gsm, wm, wn, lane, acc);
    __syncthreads();

    // ---- fused cell update; stage new h tile (fp16, swizzled, 16 KB) ----
    char* hstg = smem + HSTG_OFF;
    const int n0g = bn >> 2;                  // first hidden unit (64 per CTA)
    const float* xp = (s < 64 ? g_XP0 : g_XP1);
    const int ss = s & 63;
    const bool last = (s == SLEN - 1);
    #pragma unroll 4
    for (int it = 0; it < 16; ++it) {
        const int row = it * 8 + (tid >> 6);
        const int n   = tid & 63;
        const float4 gv = *reinterpret_cast<const float4*>(&gsm[row * GS + 4 * n]);
        const float4 xv = *reinterpret_cast<const float4*>(
            &xp[((size_t)(bm + row) * 64 + ss) * NGC + bn + 4 * n]);
        const float ig = sigm(gv.x + xv.x);
        const float fg = sigm(gv.y + xv.y);
        const float gg = tanh_f(gv.z + xv.z);
        const float og = sigm(gv.w + xv.w);
        const size_t gi = (size_t)(bm + row) * HID + n0g + n;
        const float cc = fg * c_g[gi] + ig * gg;
        c_g[gi] = cc;
        const float hh = og * tanh_f(cc);
        if (last) h_g[gi] = hh;
        *reinterpret_cast<__half*>(hstg + sw(row, n >> 3) + (n & 7) * 2)
            = __float2half_rn(hh);
    }
    __syncthreads();
    if (tid == 0) {
        asm volatile("fence.proxy.async.shared::cta;" ::: "memory");
        bulk_st(g_HaT[wrbuf] + (size_t)blockIdx.y * MT_H + (size_t)(n0g >> 6) * A_TILE_H,
                smem_u32(hstg), A_TILE_B);
        asm volatile("cp.async.bulk.commit_group;" ::: "memory");
        asm volatile("cp.async.bulk.wait_group 0;" ::: "memory");
    }
    __syncthreads();
}

// ---------------------------------------------------------------------------
extern "C" void kernel_launch(void* const* d_in, const int* in_sizes, int n_in,
                              void* d_out, int out_size)
{
    const float* x = nullptr;
    const float* w[8] = {nullptr};
    const float* b[8] = {nullptr};
    int wi = 0, bi = 0;
    for (int i = 0; i < n_in; ++i) {
        const int sz = in_sizes[i];
        if (sz == HID * HID)      { if (wi < 8) w[wi++] = (const float*)d_in[i]; }
        else if (sz == HID)       { if (bi < 8) b[bi++] = (const float*)d_in[i]; }
        else                      { x = (const float*)d_in[i]; }
    }

    float* h = (float*)d_out;
    float* c = h + (size_t)HID * HID;

    cudaFuncSetAttribute(xproj_gemm, cudaFuncAttributeMaxDynamicSharedMemorySize, SMEM_B);
    cudaFuncSetAttribute(lstm_step,  cudaFuncAttributeMaxDynamicSharedMemorySize, SMEM_B);

    prep_weights<<<(NGC * 128 + 255) / 256, 256>>>(
        w[0], w[1], w[2], w[3], w[4], w[5], w[6], w[7]);
    {
        const size_t total = (size_t)HID * SLEN * 128;
        prep_x<<<(unsigned)((total + 255) / 256), 256>>>(x);
    }
    prep_state<<<(HID * HID) / 256, 256>>>(
        b[0], b[1], b[2], b[3], b[4], b[5], b[6], b[7], c);

    {
        dim3 grid(NGC / BN, HID);                 // 16 x 1024
        xproj_gemm<<<grid, 512, SMEM_B>>>();
    }
    dim3 grid(NGC / BN, HID / BM);                // 16 x 8 = 128 CTAs
    for (int s = 0; s < SLEN; ++s)
        lstm_step<<<grid, 512, SMEM_B>>>(s, h, c);
}

// round 10
// speedup vs baseline: 1.2988x; 1.0854x over previous
#include <cuda_runtime.h>
#include <cuda_fp16.h>
#include <cstdint>
#include <cstddef>

// LSTM: B == H == 1024, S = 128, I = 1024.
//   XP[.]  = x @ Wx + bias   (one parallel GEMM, fp16 tiled output)
//   step s: gates = h @ Wh + XP ; fused cell (c in registers), persistent kernel
// fp16 single-product mma.sync. Producer warp (17th) drives cp.async.bulk ring;
// weights prefetched across the step boundary; grid barrier between steps.
// Gate columns interleaved: col' = 4n+g  (g: 0=i,1=f,2=g,3=o).

#define HID  1024
#define SLEN 128
#define NGC  4096
#define KH   1024

#define BM 128
#define BN 256
#define BK 64
#define NSLAB  (KH / BK)     // 16
#define NSTAGE 4

#define A_TILE_B 16384       // 128 x 64 fp16
#define B_TILE_B 32768       // 256 x 64 fp16
#define STAGE_B  (A_TILE_B + B_TILE_B)   // 49152
#define RING_B   (NSTAGE * STAGE_B)      // 196608
#define HSTG_OFF RING_B
#define SMEM_P   (RING_B + A_TILE_B)     // 212992 (persistent kernel)
#define GS 260
#define SMEM_X   RING_B                  // xproj (gates gsm overlays ring)

#define A_TILE_H 8192
#define B_TILE_H 16384
#define MT_H (NSLAB * A_TILE_H)   // 131072
#define NT_H (NSLAB * B_TILE_H)   // 262144

#define NCTA 128

// ---- static device scratch (each < 2GB) ----
__device__ __align__(1024) __half g_WhT[(size_t)16 * NT_H];
__device__ __align__(1024) __half g_WxT[(size_t)16 * NT_H];
__device__ __align__(1024) __half g_XT[(size_t)HID * MT_H];
__device__ __align__(1024) __half g_HaT[2][(size_t)8 * MT_H];
__device__ float g_bias[NGC];
__device__ uint2 g_XP[(size_t)128 * 128 * 8192];   // [ctile][s][row][u] half4, 1 GiB
__device__ unsigned g_cnt;

// ---- helpers ----
__device__ __forceinline__ uint32_t smem_u32(const void* p) {
    uint32_t a;
    asm("{ .reg .u64 t; cvta.to.shared.u64 t, %1; cvt.u32.u64 %0, t; }" : "=r"(a) : "l"(p));
    return a;
}
__device__ __forceinline__ void mbar_init(uint32_t bar, uint32_t cnt) {
    asm volatile("mbarrier.init.shared.b64 [%0], %1;" :: "r"(bar), "r"(cnt) : "memory");
}
__device__ __forceinline__ void mbar_arrive(uint32_t bar) {
    asm volatile("mbarrier.arrive.shared.b64 _, [%0];" :: "r"(bar) : "memory");
}
__device__ __forceinline__ void mbar_wait(uint32_t bar, uint32_t parity) {
    asm volatile(
        "{\n\t.reg .pred P;\n\tWL_%=:\n\t"
        "mbarrier.try_wait.parity.acquire.cta.shared::cta.b64 P, [%0], %1, 0x989680;\n\t"
        "@P bra.uni WD_%=;\n\tbra.uni WL_%=;\n\tWD_%=:\n\t}"
        :: "r"(bar), "r"(parity) : "memory");
}
__device__ __forceinline__ void expect_tx(uint32_t bar, uint32_t bytes) {
    asm volatile("mbarrier.arrive.expect_tx.shared.b64 _, [%0], %1;"
                 :: "r"(bar), "r"(bytes) : "memory");
}
__device__ __forceinline__ void bulk_ld(uint32_t dst, const void* src,
                                        uint32_t bytes, uint32_t bar) {
    asm volatile(
        "cp.async.bulk.shared::cluster.global.mbarrier::complete_tx::bytes "
        "[%0], [%1], %2, [%3];"
        :: "r"(dst), "l"(src), "r"(bytes), "r"(bar) : "memory");
}
__device__ __forceinline__ void bulk_st(void* dst, uint32_t src, uint32_t bytes) {
    asm volatile("cp.async.bulk.global.shared::cta.bulk_group [%0], [%1], %2;"
        :: "l"(dst), "r"(src), "r"(bytes) : "memory");
}
#define FENCE_ASYNC() asm volatile("fence.proxy.async;" ::: "memory")
__device__ __forceinline__ void ldm_x4(uint32_t* r, uint32_t addr) {
    asm volatile("ldmatrix.sync.aligned.m8n8.x4.shared.b16 {%0,%1,%2,%3}, [%4];"
        : "=r"(r[0]), "=r"(r[1]), "=r"(r[2]), "=r"(r[3]) : "r"(addr));
}
__device__ __forceinline__ void mma16816(float* c, const uint32_t* a, const uint32_t* b) {
    asm volatile(
        "mma.sync.aligned.m16n8k16.row.col.f32.f16.f16.f32 "
        "{%0,%1,%2,%3}, {%4,%5,%6,%7}, {%8,%9}, {%0,%1,%2,%3};\n"
        : "+f"(c[0]), "+f"(c[1]), "+f"(c[2]), "+f"(c[3])
        : "r"(a[0]), "r"(a[1]), "r"(a[2]), "r"(a[3]), "r"(b[0]), "r"(b[1]));
}
__device__ __forceinline__ uint32_t sw(int row, int q) {
    return (uint32_t)(row * 128 + ((q ^ (row & 7)) << 4));
}
__device__ __forceinline__ float sigm(float x) { return 1.0f / (1.0f + __expf(-x)); }
__device__ __forceinline__ float tanh_f(float x) { return 1.0f - 2.0f / (__expf(2.0f * x) + 1.0f); }

__device__ __forceinline__ void slab_mma(
    uint32_t stb, int wm, int wn, int lane, float acc[2][8][4])
{
    #pragma unroll
    for (int kk = 0; kk < 4; ++kk) {
        uint32_t ra[2][4];
        #pragma unroll
        for (int mt = 0; mt < 2; ++mt) {
            const int row = wm * 32 + mt * 16 + (lane & 15);
            const int q   = kk * 2 + (lane >> 4);
            ldm_x4(ra[mt], stb + sw(row, q));
        }
        #pragma unroll
        for (int p = 0; p < 4; ++p) {
            const int row = wn * 64 + p * 16 + (lane & 7) + ((lane >> 4) << 3);
            const int q   = kk * 2 + ((lane >> 3) & 1);
            uint32_t rb[4];
            ldm_x4(rb, stb + A_TILE_B + sw(row, q));
            #pragma unroll
            for (int mt = 0; mt < 2; ++mt) {
                mma16816(acc[mt][2 * p],     ra[mt], rb);
                mma16816(acc[mt][2 * p + 1], ra[mt], rb + 2);
            }
        }
    }
}

// ---------------------------------------------------------------------------
// Prep kernels
// ---------------------------------------------------------------------------
__global__ void prep_weights(
    const float* __restrict__ w_ii, const float* __restrict__ w_hi,
    const float* __restrict__ w_if, const float* __restrict__ w_hf,
    const float* __restrict__ w_ig, const float* __restrict__ w_hg,
    const float* __restrict__ w_io, const float* __restrict__ w_ho)
{
    int idx = blockIdx.x * blockDim.x + threadIdx.x;
    if (idx >= NGC * 128) return;
    const int colp = idx >> 7;
    const int c8   = idx & 127;
    const int n    = colp >> 2;
    const int g    = colp & 3;
    const int slab = c8 >> 3, q = c8 & 7;
    const int k0   = c8 * 8;
    const int nt   = colp >> 8, trow = colp & 255;
    const size_t byteoff = (size_t)nt * (NT_H * 2) + (size_t)slab * B_TILE_B + sw(trow, q);
    const float* wh = (g == 0) ? w_hi : (g == 1) ? w_hf : (g == 2) ? w_hg : w_ho;
    const float* wx = (g == 0) ? w_ii : (g == 1) ? w_if : (g == 2) ? w_ig : w_io;
    __half vh[8], vx[8];
    #pragma unroll
    for (int j = 0; j < 8; ++j) {
        vh[j] = __float2half_rn(wh[(size_t)(k0 + j) * HID + n]);
        vx[j] = __float2half_rn(wx[(size_t)(k0 + j) * HID + n]);
    }
    *reinterpret_cast<uint4*>(reinterpret_cast<char*>(g_WhT) + byteoff) =
        *reinterpret_cast<const uint4*>(vh);
    *reinterpret_cast<uint4*>(reinterpret_cast<char*>(g_WxT) + byteoff) =
        *reinterpret_cast<const uint4*>(vx);
}

__global__ void prep_x(const float* __restrict__ x)
{
    size_t idx = (size_t)blockIdx.x * blockDim.x + threadIdx.x;
    if (idx >= (size_t)HID * SLEN * 128) return;
    const int b   = (int)(idx >> 14);
    const int s   = (int)((idx >> 7) & 127);
    const int c8  = (int)(idx & 127);
    const int slab = c8 >> 3, q = c8 & 7;
    const float* src = x + ((size_t)b * SLEN + s) * HID + c8 * 8;
    __half v[8];
    #pragma unroll
    for (int j = 0; j < 8; ++j) v[j] = __float2half_rn(src[j]);
    const size_t byteoff = (size_t)b * (MT_H * 2) + (size_t)slab * A_TILE_B + sw(s, q);
    *reinterpret_cast<uint4*>(reinterpret_cast<char*>(g_XT) + byteoff) =
        *reinterpret_cast<const uint4*>(v);
}

__global__ void prep_state(
    const float* __restrict__ b_ii, const float* __restrict__ b_hi,
    const float* __restrict__ b_if, const float* __restrict__ b_hf,
    const float* __restrict__ b_ig, const float* __restrict__ b_hg,
    const float* __restrict__ b_io, const float* __restrict__ b_ho)
{
    int idx = blockIdx.x * blockDim.x + threadIdx.x;
    if (idx == 0) g_cnt = 0u;
    if (idx < (int)(8 * MT_H / 2))
        reinterpret_cast<uint32_t*>(g_HaT[0])[idx] = 0u;
    if (idx < NGC) {
        int n = idx >> 2, g = idx & 3;
        const float* bi = (g == 0) ? b_ii : (g == 1) ? b_if : (g == 2) ? b_ig : b_io;
        const float* bh = (g == 0) ? b_hi : (g == 1) ? b_hf : (g == 2) ? b_hg : b_ho;
        g_bias[idx] = bi[n] + bh[n];
    }
}

// ---------------------------------------------------------------------------
// xproj: XP = x @ Wx + bias -> fp16 half4 tiled [ctile][s][row][u]
// grid (16, 1024): blockIdx.y = batch b (its 128 M-rows are s = 0..127)
// ---------------------------------------------------------------------------
__global__ __launch_bounds__(512, 1) void xproj_gemm()
{
    extern __shared__ __align__(128) char smem[];
    __shared__ __align__(8) uint64_t barr[8];
    __shared__ __align__(16) float sbias[BN];

    const int tid  = threadIdx.x;
    const int lane = tid & 31;
    const int warp = tid >> 5;
    const int wm   = warp >> 2;
    const int wn   = warp & 3;
    const int bn   = blockIdx.x * BN;
    const int bt   = blockIdx.y;
    const uint32_t sbase = smem_u32(smem);
    const uint32_t fb0   = smem_u32(barr);

    if (tid == 0) {
        #pragma unroll
        for (int i = 0; i < NSTAGE; ++i) {
            mbar_init(fb0 + i * 8, 1);
            mbar_init(fb0 + 32 + i * 8, 16);
        }
        FENCE_ASYNC();
    }
    if (tid < BN) sbias[tid] = g_bias[bn + tid];
    __syncthreads();

    float acc[2][8][4];
    #pragma unroll
    for (int a = 0; a < 2; ++a)
        #pragma unroll
        for (int b = 0; b < 8; ++b)
            #pragma unroll
            for (int v = 0; v < 4; ++v) acc[a][b][v] = 0.0f;

    const __half* aT = g_XT + (size_t)bt * MT_H;
    const __half* bT = g_WxT + (size_t)blockIdx.x * NT_H;
    if (tid == 0) {
        #pragma unroll
        for (int i = 0; i < NSTAGE; ++i) {
            expect_tx(fb0 + i * 8, STAGE_B);
            bulk_ld(sbase + i * STAGE_B,            aT + i * A_TILE_H, A_TILE_B, fb0 + i * 8);
            bulk_ld(sbase + i * STAGE_B + A_TILE_B, bT + i * B_TILE_H, B_TILE_B, fb0 + i * 8);
        }
    }
    for (int kt = 0; kt < NSLAB; ++kt) {
        const int st = kt & 3;
        const int m  = kt >> 2;
        mbar_wait(fb0 + st * 8, m & 1);
        slab_mma(sbase + st * STAGE_B, wm, wn, lane, acc);
        if (lane == 0) mbar_arrive(fb0 + 32 + st * 8);
        if (tid == 0 && kt + NSTAGE < NSLAB) {
            mbar_wait(fb0 + 32 + st * 8, m & 1);
            const int k2 = kt + NSTAGE;
            expect_tx(fb0 + st * 8, STAGE_B);
            bulk_ld(sbase + st * STAGE_B,            aT + k2 * A_TILE_H, A_TILE_B, fb0 + st * 8);
            bulk_ld(sbase + st * STAGE_B + A_TILE_B, bT + k2 * B_TILE_H, B_TILE_B, fb0 + st * 8);
        }
    }
    __syncthreads();

    // stage gates to smem, then store fp16 half4 to tiled XP
    float* gsm = (float*)smem;
    #pragma unroll
    for (int mt = 0; mt < 2; ++mt) {
        const int row = wm * 32 + mt * 16 + (lane >> 2);
        #pragma unroll
        for (int nt = 0; nt < 8; ++nt) {
            const int c0 = wn * 64 + nt * 8 + 2 * (lane & 3);
            *reinterpret_cast<float2*>(&gsm[row * GS + c0]) =
                make_float2(acc[mt][nt][0], acc[mt][nt][1]);
            *reinterpret_cast<float2*>(&gsm[(row + 8) * GS + c0]) =
                make_float2(acc[mt][nt][2], acc[mt][nt][3]);
        }
    }
    __syncthreads();

    const int bmt = bt >> 7, brow = bt & 127;
    #pragma unroll 4
    for (int it = 0; it < 16; ++it) {
        const int srow = it * 8 + (tid >> 6);
        const int n    = tid & 63;
        const float4 gv = *reinterpret_cast<const float4*>(&gsm[srow * GS + 4 * n]);
        const float4 bv = *reinterpret_cast<const float4*>(&sbias[4 * n]);
        __half2 lo = __floats2half2_rn(gv.x + bv.x, gv.y + bv.y);
        __half2 hi = __floats2half2_rn(gv.z + bv.z, gv.w + bv.w);
        uint2 val;
        val.x = *reinterpret_cast<uint32_t*>(&lo);
        val.y = *reinterpret_cast<uint32_t*>(&hi);
        g_XP[((size_t)((bmt * 16 + blockIdx.x) * 128 + srow) * 128 + brow) * 64 + n] = val;
    }
}

// ---------------------------------------------------------------------------
// Persistent recurrence: 128 CTAs, 544 threads (16 consumer warps + producer)
// ---------------------------------------------------------------------------
__global__ __launch_bounds__(544, 1) void lstm_persistent(
    float* __restrict__ h_g, float* __restrict__ c_g)
{
    extern __shared__ __align__(128) char smem[];
    __shared__ __align__(8) uint64_t barr[8];

    const int tid  = threadIdx.x;
    const int lane = tid & 31;
    const int warp = tid >> 5;
    const int wm   = warp >> 2;
    const int wn   = warp & 3;
    const int bm   = blockIdx.y * BM;
    const uint32_t sbase = smem_u32(smem);
    const uint32_t fb0   = smem_u32(barr);
    const uint32_t hstga = sbase + HSTG_OFF;
    const __half* bT = g_WhT + (size_t)blockIdx.x * NT_H;
    const int n0g = blockIdx.x * 64;

    if (tid == 0) {
        #pragma unroll
        for (int i = 0; i < NSTAGE; ++i) {
            mbar_init(fb0 + i * 8, 1);        // full
            mbar_init(fb0 + 32 + i * 8, 16);  // empty
        }
        FENCE_ASYNC();
    }
    __syncthreads();

    float acc[2][8][4];
    #pragma unroll
    for (int a = 0; a < 2; ++a)
        #pragma unroll
        for (int b = 0; b < 8; ++b)
            #pragma unroll
            for (int v = 0; v < 4; ++v) acc[a][b][v] = 0.0f;
    float c_reg[16];
    #pragma unroll
    for (int i = 0; i < 16; ++i) c_reg[i] = 0.0f;

    for (int s = 0; s < SLEN; ++s) {
        const int rdbuf = s & 1;

        // ---- mainloop (skipped at s=0: h=0 => gates = XP) ----
        if (s > 0) {
            if (warp < 16) {
                for (int kt = 0; kt < NSLAB; ++kt) {
                    const int st = kt & 3;
                    mbar_wait(fb0 + st * 8, (kt >> 2) & 1);
                    slab_mma(sbase + st * STAGE_B, wm, wn, lane, acc);
                    if (lane == 0) mbar_arrive(fb0 + 32 + st * 8);
                }
            } else if (tid == 512) {
                const __half* aT = g_HaT[rdbuf] + (size_t)blockIdx.y * MT_H;
                for (int kt = 0; kt < NSLAB; ++kt) {
                    const int st = kt & 3;
                    mbar_wait(fb0 + 32 + st * 8, (kt >> 2) & 1);
                    if (kt < NSLAB - NSTAGE) {
                        const int k2 = kt + NSTAGE;
                        expect_tx(fb0 + st * 8, STAGE_B);
                        bulk_ld(sbase + st * STAGE_B,            aT + k2 * A_TILE_H, A_TILE_B, fb0 + st * 8);
                        bulk_ld(sbase + st * STAGE_B + A_TILE_B, bT + k2 * B_TILE_H, B_TILE_B, fb0 + st * 8);
                    } else if (s + 1 < SLEN) {
                        // boundary: prefetch NEXT step's B now; A after grid barrier
                        const int k2 = kt - (NSLAB - NSTAGE);
                        expect_tx(fb0 + st * 8, STAGE_B);
                        bulk_ld(sbase + st * STAGE_B + A_TILE_B, bT + k2 * B_TILE_H, B_TILE_B, fb0 + st * 8);
                    }
                }
            }
        }

        // ---- fused cell update (shuffle-gathered gates; c in registers) ----
        if (warp < 16) {
            const uint2* xpb = g_XP +
                ((size_t)(blockIdx.y * 16 + blockIdx.x) * 128 + s) * 8192;
            const int odd = lane & 1;
            const int rb  = wm * 32 + (lane >> 2) + (odd ? 8 : 0);
            const bool last = (s == SLEN - 1);
            #pragma unroll
            for (int mt = 0; mt < 2; ++mt) {
                #pragma unroll
                for (int nt = 0; nt < 8; ++nt) {
                    float v0 = acc[mt][nt][0], v1 = acc[mt][nt][1];
                    float v2 = acc[mt][nt][2], v3 = acc[mt][nt][3];
                    const float s0 = __shfl_xor_sync(0xffffffffu, v0, 1);
                    const float s1 = __shfl_xor_sync(0xffffffffu, v1, 1);
                    const float s2 = __shfl_xor_sync(0xffffffffu, v2, 1);
                    const float s3 = __shfl_xor_sync(0xffffffffu, v3, 1);
                    const int row = rb + mt * 16;
                    const int u   = wn * 16 + nt * 2 + ((lane & 3) >> 1);
                    float xi = odd ? s2 : v0;
                    float xf = odd ? s3 : v1;
                    float xg = odd ? v2 : s0;
                    float xo = odd ? v3 : s1;
                    const uint2 xv = xpb[row * 64 + u];
                    const __half2 l2 = *reinterpret_cast<const __half2*>(&xv.x);
                    const __half2 h2 = *reinterpret_cast<const __half2*>(&xv.y);
                    xi += __low2float(l2);  xf += __high2float(l2);
                    xg += __low2float(h2);  xo += __high2float(h2);
                    const float ig = sigm(xi), fg = sigm(xf);
                    const float gg = tanh_f(xg), og = sigm(xo);
                    const float cc = fg * c_reg[mt * 8 + nt] + ig * gg;
                    c_reg[mt * 8 + nt] = cc;
                    const float hh = og * tanh_f(cc);
                    *reinterpret_cast<__half*>(smem + HSTG_OFF + sw(row, u >> 3) + (u & 7) * 2)
                        = __float2half_rn(hh);
                    if (last) {
                        const size_t gi = (size_t)(bm + row) * HID + n0g + u;
                        h_g[gi] = hh;
                        c_g[gi] = cc;
                    }
                    acc[mt][nt][0] = 0.0f; acc[mt][nt][1] = 0.0f;
                    acc[mt][nt][2] = 0.0f; acc[mt][nt][3] = 0.0f;
                }
            }
        }
        __syncthreads();

        // ---- store h tile, grid barrier, issue next step's A (and s=0: A+B) ----
        if (tid == 512 && s + 1 < SLEN) {
            FENCE_ASYNC();
            bulk_st(g_HaT[rdbuf ^ 1] + (size_t)blockIdx.y * MT_H
                        + (size_t)blockIdx.x * A_TILE_H,
                    hstga, A_TILE_B);
            asm volatile("cp.async.bulk.commit_group;" ::: "memory");
            asm volatile("cp.async.bulk.wait_group 0;" ::: "memory");
            __threadfence();
            atomicAdd(&g_cnt, 1u);
            const unsigned target = (unsigned)(s + 1) * NCTA;
            unsigned v;
            do {
                asm volatile("ld.acquire.gpu.global.u32 %0, [%1];"
                             : "=r"(v) : "l"(&g_cnt) : "memory");
            } while (v < target);
            FENCE_ASYNC();
            const __half* aTn = g_HaT[rdbuf ^ 1] + (size_t)blockIdx.y * MT_H;
            if (s == 0) {
                #pragma unroll
                for (int st = 0; st < NSTAGE; ++st) {
                    expect_tx(fb0 + st * 8, STAGE_B);
                    bulk_ld(sbase + st * STAGE_B,            aTn + st * A_TILE_H, A_TILE_B, fb0 + st * 8);
                    bulk_ld(sbase + st * STAGE_B + A_TILE_B, bT  + st * B_TILE_H, B_TILE_B, fb0 + st * 8);
                }
            } else {
                #pragma unroll
                for (int st = 0; st < NSTAGE; ++st)
                    bulk_ld(sbase + st * STAGE_B, aTn + st * A_TILE_H, A_TILE_B, fb0 + st * 8);
            }
        }
        __syncthreads();
    }
}

// ---------------------------------------------------------------------------
extern "C" void kernel_launch(void* const* d_in, const int* in_sizes, int n_in,
                              void* d_out, int out_size)
{
    const float* x = nullptr;
    const float* w[8] = {nullptr};
    const float* b[8] = {nullptr};
    int wi = 0, bi = 0;
    for (int i = 0; i < n_in; ++i) {
        const int sz = in_sizes[i];
        if (sz == HID * HID)      { if (wi < 8) w[wi++] = (const float*)d_in[i]; }
        else if (sz == HID)       { if (bi < 8) b[bi++] = (const float*)d_in[i]; }
        else                      { x = (const float*)d_in[i]; }
    }

    float* h = (float*)d_out;
    float* c = h + (size_t)HID * HID;

    cudaFuncSetAttribute(xproj_gemm,      cudaFuncAttributeMaxDynamicSharedMemorySize, SMEM_X);
    cudaFuncSetAttribute(lstm_persistent, cudaFuncAttributeMaxDynamicSharedMemorySize, SMEM_P);

    prep_weights<<<(NGC * 128 + 255) / 256, 256>>>(
        w[0], w[1], w[2], w[3], w[4], w[5], w[6], w[7]);
    {
        const size_t total = (size_t)HID * SLEN * 128;
        prep_x<<<(unsigned)((total + 255) / 256), 256>>>(x);
    }
    prep_state<<<(HID * HID) / 256, 256>>>(
        b[0], b[1], b[2], b[3], b[4], b[5], b[6], b[7]);

    {
        dim3 grid(NGC / BN, HID);                 // 16 x 1024
        xproj_gemm<<<grid, 512, SMEM_X>>>();
    }
    {
        dim3 grid(NGC / BN, HID / BM);            // 16 x 8 = 128 CTAs, 1/SM
        lstm_persistent<<<grid, 544, SMEM_P>>>(h, c);
    }
}

// round 11
// speedup vs baseline: 1.4020x; 1.0795x over previous
#include <cuda_runtime.h>
#include <cuda_fp16.h>
#include <cstdint>
#include <cstddef>

// LSTM: B == H == 1024, S = 128, I = 1024.
// Single persistent kernel. Per step s:
//   gates = x_s @ Wx + h_{s-1} @ Wh + bias   (32 k-slabs: 16 x, then 16 h)
// x-slabs are barrier-independent -> producer defers the grid-barrier spin
// until just before the first h-slab issue; consumers never stall on it.
// fp16 single-product mma.sync, fused cell (c in registers).
// Gate columns interleaved: col' = 4n+g  (g: 0=i,1=f,2=g,3=o).

#define HID  1024
#define SLEN 128
#define NGC  4096

#define BM 128
#define BN 256
#define BK 64
#define NSK 16               // slabs per K=1024 half
#define NSTAGE 4

#define A_TILE_B 16384       // 128 x 64 fp16
#define B_TILE_B 32768       // 256 x 64 fp16
#define STAGE_B  (A_TILE_B + B_TILE_B)   // 49152
#define RING_B   (NSTAGE * STAGE_B)      // 196608
#define HSTG_OFF RING_B
#define SMEM_P   (RING_B + A_TILE_B)     // 212992

#define A_TILE_H 8192
#define B_TILE_H 16384
#define MT_H (NSK * A_TILE_H)   // 131072 halfs per h m-tile
#define NT_H (NSK * B_TILE_H)   // 262144 halfs per B n-tile

#define NCTA 128

// ---- static device scratch (each < 2GB) ----
__device__ __align__(1024) __half g_WhT[(size_t)16 * NT_H];          // 8 MB
__device__ __align__(1024) __half g_WxT[(size_t)16 * NT_H];          // 8 MB
__device__ __align__(1024) __half g_XT[(size_t)8 * SLEN * NSK * A_TILE_H]; // 256 MB [mt][s][slab]
__device__ __align__(1024) __half g_HaT[2][(size_t)8 * MT_H];        // 2 MB each
__device__ float g_bias[NGC];
__device__ unsigned g_cnt;

// ---- helpers ----
__device__ __forceinline__ uint32_t smem_u32(const void* p) {
    uint32_t a;
    asm("{ .reg .u64 t; cvta.to.shared.u64 t, %1; cvt.u32.u64 %0, t; }" : "=r"(a) : "l"(p));
    return a;
}
__device__ __forceinline__ void mbar_init(uint32_t bar, uint32_t cnt) {
    asm volatile("mbarrier.init.shared.b64 [%0], %1;" :: "r"(bar), "r"(cnt) : "memory");
}
__device__ __forceinline__ void mbar_arrive(uint32_t bar) {
    asm volatile("mbarrier.arrive.shared.b64 _, [%0];" :: "r"(bar) : "memory");
}
__device__ __forceinline__ void mbar_wait(uint32_t bar, uint32_t parity) {
    asm volatile(
        "{\n\t.reg .pred P;\n\tWL_%=:\n\t"
        "mbarrier.try_wait.parity.acquire.cta.shared::cta.b64 P, [%0], %1, 0x989680;\n\t"
        "@P bra.uni WD_%=;\n\tbra.uni WL_%=;\n\tWD_%=:\n\t}"
        :: "r"(bar), "r"(parity) : "memory");
}
__device__ __forceinline__ void expect_tx(uint32_t bar, uint32_t bytes) {
    asm volatile("mbarrier.arrive.expect_tx.shared.b64 _, [%0], %1;"
                 :: "r"(bar), "r"(bytes) : "memory");
}
__device__ __forceinline__ void bulk_ld(uint32_t dst, const void* src,
                                        uint32_t bytes, uint32_t bar) {
    asm volatile(
        "cp.async.bulk.shared::cluster.global.mbarrier::complete_tx::bytes "
        "[%0], [%1], %2, [%3];"
        :: "r"(dst), "l"(src), "r"(bytes), "r"(bar) : "memory");
}
__device__ __forceinline__ void bulk_st(void* dst, uint32_t src, uint32_t bytes) {
    asm volatile("cp.async.bulk.global.shared::cta.bulk_group [%0], [%1], %2;"
        :: "l"(dst), "r"(src), "r"(bytes) : "memory");
}
#define FENCE_ASYNC() asm volatile("fence.proxy.async;" ::: "memory")
__device__ __forceinline__ void ldm_x4(uint32_t* r, uint32_t addr) {
    asm volatile("ldmatrix.sync.aligned.m8n8.x4.shared.b16 {%0,%1,%2,%3}, [%4];"
        : "=r"(r[0]), "=r"(r[1]), "=r"(r[2]), "=r"(r[3]) : "r"(addr));
}
__device__ __forceinline__ void mma16816(float* c, const uint32_t* a, const uint32_t* b) {
    asm volatile(
        "mma.sync.aligned.m16n8k16.row.col.f32.f16.f16.f32 "
        "{%0,%1,%2,%3}, {%4,%5,%6,%7}, {%8,%9}, {%0,%1,%2,%3};\n"
        : "+f"(c[0]), "+f"(c[1]), "+f"(c[2]), "+f"(c[3])
        : "r"(a[0]), "r"(a[1]), "r"(a[2]), "r"(a[3]), "r"(b[0]), "r"(b[1]));
}
__device__ __forceinline__ uint32_t sw(int row, int q) {
    return (uint32_t)(row * 128 + ((q ^ (row & 7)) << 4));
}
__device__ __forceinline__ float sigm(float x) { return 1.0f / (1.0f + __expf(-x)); }
__device__ __forceinline__ float tanh_f(float x) { return 1.0f - 2.0f / (__expf(2.0f * x) + 1.0f); }

__device__ __forceinline__ void slab_mma(
    uint32_t stb, int wm, int wn, int lane, float acc[2][8][4])
{
    #pragma unroll
    for (int kk = 0; kk < 4; ++kk) {
        uint32_t ra[2][4];
        #pragma unroll
        for (int mt = 0; mt < 2; ++mt) {
            const int row = wm * 32 + mt * 16 + (lane & 15);
            const int q   = kk * 2 + (lane >> 4);
            ldm_x4(ra[mt], stb + sw(row, q));
        }
        #pragma unroll
        for (int p = 0; p < 4; ++p) {
            const int row = wn * 64 + p * 16 + (lane & 7) + ((lane >> 4) << 3);
            const int q   = kk * 2 + ((lane >> 3) & 1);
            uint32_t rb[4];
            ldm_x4(rb, stb + A_TILE_B + sw(row, q));
            #pragma unroll
            for (int mt = 0; mt < 2; ++mt) {
                mma16816(acc[mt][2 * p],     ra[mt], rb);
                mma16816(acc[mt][2 * p + 1], ra[mt], rb + 2);
            }
        }
    }
}

// ---------------------------------------------------------------------------
// Prep kernels
// ---------------------------------------------------------------------------
__global__ void prep_weights(
    const float* __restrict__ w_ii, const float* __restrict__ w_hi,
    const float* __restrict__ w_if, const float* __restrict__ w_hf,
    const float* __restrict__ w_ig, const float* __restrict__ w_hg,
    const float* __restrict__ w_io, const float* __restrict__ w_ho)
{
    int idx = blockIdx.x * blockDim.x + threadIdx.x;
    if (idx >= NGC * 128) return;
    const int colp = idx >> 7;           // col' = 4n+g
    const int c8   = idx & 127;          // 16B chunk; k0 = c8*8
    const int n    = colp >> 2;
    const int g    = colp & 3;
    const int slab = c8 >> 3, q = c8 & 7;
    const int k0   = c8 * 8;
    const int nt   = colp >> 8, trow = colp & 255;
    const size_t byteoff = (size_t)nt * (NT_H * 2) + (size_t)slab * B_TILE_B + sw(trow, q);
    const float* wh = (g == 0) ? w_hi : (g == 1) ? w_hf : (g == 2) ? w_hg : w_ho;
    const float* wx = (g == 0) ? w_ii : (g == 1) ? w_if : (g == 2) ? w_ig : w_io;
    __half vh[8], vx[8];
    #pragma unroll
    for (int j = 0; j < 8; ++j) {
        vh[j] = __float2half_rn(wh[(size_t)(k0 + j) * HID + n]);
        vx[j] = __float2half_rn(wx[(size_t)(k0 + j) * HID + n]);
    }
    *reinterpret_cast<uint4*>(reinterpret_cast<char*>(g_WhT) + byteoff) =
        *reinterpret_cast<const uint4*>(vh);
    *reinterpret_cast<uint4*>(reinterpret_cast<char*>(g_WxT) + byteoff) =
        *reinterpret_cast<const uint4*>(vx);
}

// x tiled per (mtile, step, slab): A tile rows = 128 batch rows of that mtile
__global__ void prep_x(const float* __restrict__ x)
{
    size_t idx = (size_t)blockIdx.x * blockDim.x + threadIdx.x;
    if (idx >= (size_t)HID * SLEN * 128) return;
    const int b   = (int)(idx >> 14);
    const int s   = (int)((idx >> 7) & 127);
    const int c8  = (int)(idx & 127);
    const int slab = c8 >> 3, q = c8 & 7;
    const float* src = x + ((size_t)b * SLEN + s) * HID + c8 * 8;
    __half v[8];
    #pragma unroll
    for (int j = 0; j < 8; ++j) v[j] = __float2half_rn(src[j]);
    const size_t byteoff =
        ((size_t)((b >> 7) * SLEN + s) * NSK + slab) * A_TILE_B + sw(b & 127, q);
    *reinterpret_cast<uint4*>(reinterpret_cast<char*>(g_XT) + byteoff) =
        *reinterpret_cast<const uint4*>(v);
}

__global__ void prep_state(
    const float* __restrict__ b_ii, const float* __restrict__ b_hi,
    const float* __restrict__ b_if, const float* __restrict__ b_hf,
    const float* __restrict__ b_ig, const float* __restrict__ b_hg,
    const float* __restrict__ b_io, const float* __restrict__ b_ho)
{
    int idx = blockIdx.x * blockDim.x + threadIdx.x;
    if (idx == 0) g_cnt = 0u;
    if (idx < NGC) {
        int n = idx >> 2, g = idx & 3;
        const float* bi = (g == 0) ? b_ii : (g == 1) ? b_if : (g == 2) ? b_ig : b_io;
        const float* bh = (g == 0) ? b_hi : (g == 1) ? b_hf : (g == 2) ? b_hg : b_ho;
        g_bias[idx] = bi[n] + bh[n];
    }
}

// ---------------------------------------------------------------------------
// Persistent kernel: 128 CTAs, 544 threads (16 consumer warps + producer warp)
// ---------------------------------------------------------------------------
__global__ __launch_bounds__(544, 1) void lstm_persistent(
    float* __restrict__ h_g, float* __restrict__ c_g)
{
    extern __shared__ __align__(128) char smem[];
    __shared__ __align__(8) uint64_t barr[8];
    __shared__ __align__(16) float sbias[BN];

    const int tid  = threadIdx.x;
    const int lane = tid & 31;
    const int warp = tid >> 5;
    const int wm   = warp >> 2;
    const int wn   = warp & 3;
    const int bm   = blockIdx.y * BM;
    const uint32_t sbase = smem_u32(smem);
    const uint32_t fb0   = smem_u32(barr);
    const uint32_t hstga = sbase + HSTG_OFF;
    const int n0g = blockIdx.x * 64;

    if (tid == 0) {
        #pragma unroll
        for (int i = 0; i < NSTAGE; ++i) {
            mbar_init(fb0 + i * 8, 1);        // full (tx)
            mbar_init(fb0 + 32 + i * 8, 16);  // empty (16 consumer warps)
        }
        FENCE_ASYNC();
    }
    if (tid < BN) sbias[tid] = g_bias[blockIdx.x * BN + tid];
    __syncthreads();

    float acc[2][8][4];
    #pragma unroll
    for (int a = 0; a < 2; ++a)
        #pragma unroll
        for (int b = 0; b < 8; ++b)
            #pragma unroll
            for (int v = 0; v < 4; ++v) acc[a][b][v] = 0.0f;
    float c_reg[16];
    #pragma unroll
    for (int i = 0; i < 16; ++i) c_reg[i] = 0.0f;

    // producer state (live only in warp 16, thread 512)
    int is = 0, ij = 0, bar_seen = 0;
    unsigned pk = 0, ck = 0;

    // producer prologue: first 4 x-slabs of step 0
    if (tid == 512) {
        #pragma unroll
        for (int i = 0; i < NSTAGE; ++i) {
            expect_tx(fb0 + i * 8, STAGE_B);
            bulk_ld(sbase + i * STAGE_B,
                    g_XT + ((size_t)(blockIdx.y * SLEN) * NSK + i) * A_TILE_H,
                    A_TILE_B, fb0 + i * 8);
            bulk_ld(sbase + i * STAGE_B + A_TILE_B,
                    g_WxT + (size_t)blockIdx.x * NT_H + (size_t)i * B_TILE_H,
                    B_TILE_B, fb0 + i * 8);
        }
        ij = NSTAGE;
    }

    for (int s = 0; s < SLEN; ++s) {
        const int NS = (s == 0) ? NSK : 2 * NSK;

        if (warp < 16) {
            // ---- consumer mainloop ----
            for (int j = 0; j < NS; ++j) {
                const int st = ck & 3;
                mbar_wait(fb0 + st * 8, (ck >> 2) & 1);
                slab_mma(sbase + st * STAGE_B, wm, wn, lane, acc);
                if (lane == 0) mbar_arrive(fb0 + 32 + st * 8);
                ++ck;
            }
            // ---- fused cell update (shuffle-gathered gates; c in regs) ----
            const int odd = lane & 1;
            const int rb  = wm * 32 + (lane >> 2) + (odd ? 8 : 0);
            const bool last = (s == SLEN - 1);
            #pragma unroll
            for (int mt = 0; mt < 2; ++mt) {
                #pragma unroll
                for (int nt = 0; nt < 8; ++nt) {
                    float v0 = acc[mt][nt][0], v1 = acc[mt][nt][1];
                    float v2 = acc[mt][nt][2], v3 = acc[mt][nt][3];
                    const float s0 = __shfl_xor_sync(0xffffffffu, v0, 1);
                    const float s1 = __shfl_xor_sync(0xffffffffu, v1, 1);
                    const float s2 = __shfl_xor_sync(0xffffffffu, v2, 1);
                    const float s3 = __shfl_xor_sync(0xffffffffu, v3, 1);
                    const int row = rb + mt * 16;
                    const int u   = wn * 16 + nt * 2 + ((lane & 3) >> 1);
                    float xi = odd ? s2 : v0;
                    float xf = odd ? s3 : v1;
                    float xg = odd ? v2 : s0;
                    float xo = odd ? v3 : s1;
                    const float4 bv = *reinterpret_cast<const float4*>(&sbias[4 * u]);
                    xi += bv.x; xf += bv.y; xg += bv.z; xo += bv.w;
                    const float ig = sigm(xi), fg = sigm(xf);
                    const float gg = tanh_f(xg), og = sigm(xo);
                    const float cc = fg * c_reg[mt * 8 + nt] + ig * gg;
                    c_reg[mt * 8 + nt] = cc;
                    const float hh = og * tanh_f(cc);
                    *reinterpret_cast<__half*>(smem + HSTG_OFF + sw(row, u >> 3) + (u & 7) * 2)
                        = __float2half_rn(hh);
                    if (last) {
                        const size_t gi = (size_t)(bm + row) * HID + n0g + u;
                        h_g[gi] = hh;
                        c_g[gi] = cc;
                    }
                    acc[mt][nt][0] = 0.0f; acc[mt][nt][1] = 0.0f;
                    acc[mt][nt][2] = 0.0f; acc[mt][nt][3] = 0.0f;
                }
            }
        } else if (tid == 512) {
            // ---- producer: wait empties, issue slab (is, ij) 4 ahead ----
            for (int j = 0; j < NS; ++j) {
                const int st = pk & 3;
                mbar_wait(fb0 + 32 + st * 8, (pk >> 2) & 1);
                if (is < SLEN) {
                    const __half *aT, *bT;
                    if (ij < NSK) {
                        aT = g_XT + ((size_t)(blockIdx.y * SLEN + is) * NSK + ij) * A_TILE_H;
                        bT = g_WxT + (size_t)blockIdx.x * NT_H + (size_t)ij * B_TILE_H;
                    } else {
                        if (bar_seen < is) {
                            // deferred grid-barrier spin: all CTAs stored h(is-1)
                            const unsigned target = (unsigned)is * NCTA;
                            unsigned v;
                            do {
                                asm volatile("ld.acquire.gpu.global.u32 %0, [%1];"
                                             : "=r"(v) : "l"(&g_cnt) : "memory");
                            } while (v < target);
                            FENCE_ASYNC();
                            bar_seen = is;
                        }
                        aT = g_HaT[is & 1] + (size_t)blockIdx.y * MT_H
                           + (size_t)(ij - NSK) * A_TILE_H;
                        bT = g_WhT + (size_t)blockIdx.x * NT_H + (size_t)(ij - NSK) * B_TILE_H;
                    }
                    expect_tx(fb0 + st * 8, STAGE_B);
                    bulk_ld(sbase + st * STAGE_B,            aT, A_TILE_B, fb0 + st * 8);
                    bulk_ld(sbase + st * STAGE_B + A_TILE_B, bT, B_TILE_B, fb0 + st * 8);
                    if (++ij == ((is == 0) ? NSK : 2 * NSK)) { ij = 0; ++is; }
                }
                ++pk;
            }
        }
        __syncthreads();   // h staging tile complete

        if (tid == 512 && s + 1 < SLEN) {
            FENCE_ASYNC();
            bulk_st(g_HaT[(s + 1) & 1] + (size_t)blockIdx.y * MT_H
                        + (size_t)blockIdx.x * A_TILE_H,
                    hstga, A_TILE_B);
            asm volatile("cp.async.bulk.commit_group;" ::: "memory");
            asm volatile("cp.async.bulk.wait_group 0;" ::: "memory");
            __threadfence();
            atomicAdd(&g_cnt, 1u);   // arrive; spin deferred to first h-slab issue
        }
        __syncthreads();
    }
}

// ---------------------------------------------------------------------------
extern "C" void kernel_launch(void* const* d_in, const int* in_sizes, int n_in,
                              void* d_out, int out_size)
{
    const float* x = nullptr;
    const float* w[8] = {nullptr};
    const float* b[8] = {nullptr};
    int wi = 0, bi = 0;
    for (int i = 0; i < n_in; ++i) {
        const int sz = in_sizes[i];
        if (sz == HID * HID)      { if (wi < 8) w[wi++] = (const float*)d_in[i]; }
        else if (sz == HID)       { if (bi < 8) b[bi++] = (const float*)d_in[i]; }
        else                      { x = (const float*)d_in[i]; }
    }

    float* h = (float*)d_out;
    float* c = h + (size_t)HID * HID;

    cudaFuncSetAttribute(lstm_persistent, cudaFuncAttributeMaxDynamicSharedMemorySize, SMEM_P);

    prep_weights<<<(NGC * 128 + 255) / 256, 256>>>(
        w[0], w[1], w[2], w[3], w[4], w[5], w[6], w[7]);
    {
        const size_t total = (size_t)HID * SLEN * 128;
        prep_x<<<(unsigned)((total + 255) / 256), 256>>>(x);
    }
    prep_state<<<(HID * HID) / 256, 256>>>(
        b[0], b[1], b[2], b[3], b[4], b[5], b[6], b[7]);

    dim3 grid(NGC / BN, HID / BM);            // 16 x 8 = 128 CTAs, 1 per SM
    lstm_persistent<<<grid, 544, SMEM_P>>>(h, c);
}

// round 12
// speedup vs baseline: 1.4822x; 1.0572x over previous
#include <cuda_runtime.h>
#include <cuda_fp16.h>
#include <cstdint>
#include <cstddef>

// LSTM: B == H == 1024, S = 128, I = 1024.
// Single persistent kernel. Per step s:
//   gates = x_s @ Wx + h_{s-1} @ Wh + bias   (32 k-slabs: 16 x, then 16 h)
// Consumers free-run across steps (epilogue-done mbarrier, no __syncthreads);
// producer warp handles h store + grid barrier, overlapped with x-GEMM.
// fp16 single-product mma.sync, fused cell (c in registers).
// Gate columns interleaved: col' = 4n+g  (g: 0=i,1=f,2=g,3=o).

#define HID  1024
#define SLEN 128
#define NGC  4096

#define BM 128
#define BN 256
#define BK 64
#define NSK 16               // slabs per K=1024 half
#define NSTAGE 4

#define A_TILE_B 16384       // 128 x 64 fp16
#define B_TILE_B 32768       // 256 x 64 fp16
#define STAGE_B  (A_TILE_B + B_TILE_B)   // 49152
#define RING_B   (NSTAGE * STAGE_B)      // 196608
#define HSTG_OFF RING_B
#define SMEM_P   (RING_B + 2 * A_TILE_B) // 229376 (double-buffered h staging)

#define A_TILE_H 8192
#define B_TILE_H 16384
#define MT_H (NSK * A_TILE_H)   // 131072 halfs per h m-tile
#define NT_H (NSK * B_TILE_H)   // 262144 halfs per B n-tile

#define NCTA 128

// ---- static device scratch (each < 2GB) ----
__device__ __align__(1024) __half g_WhT[(size_t)16 * NT_H];          // 8 MB
__device__ __align__(1024) __half g_WxT[(size_t)16 * NT_H];          // 8 MB
__device__ __align__(1024) __half g_XT[(size_t)8 * SLEN * NSK * A_TILE_H]; // 256 MB
__device__ __align__(1024) __half g_HaT[2][(size_t)8 * MT_H];        // 2 MB each
__device__ float g_bias[NGC];
__device__ unsigned g_cnt;

// ---- helpers ----
__device__ __forceinline__ uint32_t smem_u32(const void* p) {
    uint32_t a;
    asm("{ .reg .u64 t; cvta.to.shared.u64 t, %1; cvt.u32.u64 %0, t; }" : "=r"(a) : "l"(p));
    return a;
}
__device__ __forceinline__ void mbar_init(uint32_t bar, uint32_t cnt) {
    asm volatile("mbarrier.init.shared.b64 [%0], %1;" :: "r"(bar), "r"(cnt) : "memory");
}
__device__ __forceinline__ void mbar_arrive(uint32_t bar) {
    asm volatile("mbarrier.arrive.shared.b64 _, [%0];" :: "r"(bar) : "memory");
}
__device__ __forceinline__ void mbar_wait(uint32_t bar, uint32_t parity) {
    asm volatile(
        "{\n\t.reg .pred P;\n\tWL_%=:\n\t"
        "mbarrier.try_wait.parity.acquire.cta.shared::cta.b64 P, [%0], %1, 0x989680;\n\t"
        "@P bra.uni WD_%=;\n\tbra.uni WL_%=;\n\tWD_%=:\n\t}"
        :: "r"(bar), "r"(parity) : "memory");
}
__device__ __forceinline__ void expect_tx(uint32_t bar, uint32_t bytes) {
    asm volatile("mbarrier.arrive.expect_tx.shared.b64 _, [%0], %1;"
                 :: "r"(bar), "r"(bytes) : "memory");
}
__device__ __forceinline__ void bulk_ld(uint32_t dst, const void* src,
                                        uint32_t bytes, uint32_t bar) {
    asm volatile(
        "cp.async.bulk.shared::cluster.global.mbarrier::complete_tx::bytes "
        "[%0], [%1], %2, [%3];"
        :: "r"(dst), "l"(src), "r"(bytes), "r"(bar) : "memory");
}
__device__ __forceinline__ void bulk_st(void* dst, uint32_t src, uint32_t bytes) {
    asm volatile("cp.async.bulk.global.shared::cta.bulk_group [%0], [%1], %2;"
        :: "l"(dst), "r"(src), "r"(bytes) : "memory");
}
#define FENCE_ASYNC() asm volatile("fence.proxy.async;" ::: "memory")
__device__ __forceinline__ void ldm_x4(uint32_t* r, uint32_t addr) {
    asm volatile("ldmatrix.sync.aligned.m8n8.x4.shared.b16 {%0,%1,%2,%3}, [%4];"
        : "=r"(r[0]), "=r"(r[1]), "=r"(r[2]), "=r"(r[3]) : "r"(addr));
}
__device__ __forceinline__ void mma16816(float* c, const uint32_t* a, const uint32_t* b) {
    asm volatile(
        "mma.sync.aligned.m16n8k16.row.col.f32.f16.f16.f32 "
        "{%0,%1,%2,%3}, {%4,%5,%6,%7}, {%8,%9}, {%0,%1,%2,%3};\n"
        : "+f"(c[0]), "+f"(c[1]), "+f"(c[2]), "+f"(c[3])
        : "r"(a[0]), "r"(a[1]), "r"(a[2]), "r"(a[3]), "r"(b[0]), "r"(b[1]));
}
__device__ __forceinline__ uint32_t sw(int row, int q) {
    return (uint32_t)(row * 128 + ((q ^ (row & 7)) << 4));
}
__device__ __forceinline__ float sigm(float x) { return 1.0f / (1.0f + __expf(-x)); }
__device__ __forceinline__ float tanh_f(float x) { return 1.0f - 2.0f / (__expf(2.0f * x) + 1.0f); }

__device__ __forceinline__ void slab_mma(
    uint32_t stb, int wm, int wn, int lane, float acc[2][8][4])
{
    #pragma unroll
    for (int kk = 0; kk < 4; ++kk) {
        uint32_t ra[2][4];
        #pragma unroll
        for (int mt = 0; mt < 2; ++mt) {
            const int row = wm * 32 + mt * 16 + (lane & 15);
            const int q   = kk * 2 + (lane >> 4);
            ldm_x4(ra[mt], stb + sw(row, q));
        }
        #pragma unroll
        for (int p = 0; p < 4; ++p) {
            const int row = wn * 64 + p * 16 + (lane & 7) + ((lane >> 4) << 3);
            const int q   = kk * 2 + ((lane >> 3) & 1);
            uint32_t rb[4];
            ldm_x4(rb, stb + A_TILE_B + sw(row, q));
            #pragma unroll
            for (int mt = 0; mt < 2; ++mt) {
                mma16816(acc[mt][2 * p],     ra[mt], rb);
                mma16816(acc[mt][2 * p + 1], ra[mt], rb + 2);
            }
        }
    }
}

// ---------------------------------------------------------------------------
// Prep kernels
// ---------------------------------------------------------------------------
__global__ void prep_weights(
    const float* __restrict__ w_ii, const float* __restrict__ w_hi,
    const float* __restrict__ w_if, const float* __restrict__ w_hf,
    const float* __restrict__ w_ig, const float* __restrict__ w_hg,
    const float* __restrict__ w_io, const float* __restrict__ w_ho)
{
    int idx = blockIdx.x * blockDim.x + threadIdx.x;
    if (idx >= NGC * 128) return;
    const int colp = idx >> 7;           // col' = 4n+g
    const int c8   = idx & 127;          // 16B chunk; k0 = c8*8
    const int n    = colp >> 2;
    const int g    = colp & 3;
    const int slab = c8 >> 3, q = c8 & 7;
    const int k0   = c8 * 8;
    const int nt   = colp >> 8, trow = colp & 255;
    const size_t byteoff = (size_t)nt * (NT_H * 2) + (size_t)slab * B_TILE_B + sw(trow, q);
    const float* wh = (g == 0) ? w_hi : (g == 1) ? w_hf : (g == 2) ? w_hg : w_ho;
    const float* wx = (g == 0) ? w_ii : (g == 1) ? w_if : (g == 2) ? w_ig : w_io;
    __half vh[8], vx[8];
    #pragma unroll
    for (int j = 0; j < 8; ++j) {
        vh[j] = __float2half_rn(wh[(size_t)(k0 + j) * HID + n]);
        vx[j] = __float2half_rn(wx[(size_t)(k0 + j) * HID + n]);
    }
    *reinterpret_cast<uint4*>(reinterpret_cast<char*>(g_WhT) + byteoff) =
        *reinterpret_cast<const uint4*>(vh);
    *reinterpret_cast<uint4*>(reinterpret_cast<char*>(g_WxT) + byteoff) =
        *reinterpret_cast<const uint4*>(vx);
}

__global__ void prep_x(const float* __restrict__ x)
{
    size_t idx = (size_t)blockIdx.x * blockDim.x + threadIdx.x;
    if (idx >= (size_t)HID * SLEN * 128) return;
    const int b   = (int)(idx >> 14);
    const int s   = (int)((idx >> 7) & 127);
    const int c8  = (int)(idx & 127);
    const int slab = c8 >> 3, q = c8 & 7;
    const float* src = x + ((size_t)b * SLEN + s) * HID + c8 * 8;
    __half v[8];
    #pragma unroll
    for (int j = 0; j < 8; ++j) v[j] = __float2half_rn(src[j]);
    const size_t byteoff =
        ((size_t)((b >> 7) * SLEN + s) * NSK + slab) * A_TILE_B + sw(b & 127, q);
    *reinterpret_cast<uint4*>(reinterpret_cast<char*>(g_XT) + byteoff) =
        *reinterpret_cast<const uint4*>(v);
}

__global__ void prep_state(
    const float* __restrict__ b_ii, const float* __restrict__ b_hi,
    const float* __restrict__ b_if, const float* __restrict__ b_hf,
    const float* __restrict__ b_ig, const float* __restrict__ b_hg,
    const float* __restrict__ b_io, const float* __restrict__ b_ho)
{
    int idx = blockIdx.x * blockDim.x + threadIdx.x;
    if (idx == 0) g_cnt = 0u;
    if (idx < NGC) {
        int n = idx >> 2, g = idx & 3;
        const float* bi = (g == 0) ? b_ii : (g == 1) ? b_if : (g == 2) ? b_ig : b_io;
        const float* bh = (g == 0) ? b_hi : (g == 1) ? b_hf : (g == 2) ? b_hg : b_ho;
        g_bias[idx] = bi[n] + bh[n];
    }
}

// ---------------------------------------------------------------------------
// Persistent kernel: 128 CTAs, 544 threads (16 consumer warps + producer warp)
// barriers: full[0..3] @ fb0+{0,8,16,24}, empty[0..3] @ fb0+{32..56},
//           epi (16 arrivals) @ fb0+64
// ---------------------------------------------------------------------------
__global__ __launch_bounds__(544, 1) void lstm_persistent(
    float* __restrict__ h_g, float* __restrict__ c_g)
{
    extern __shared__ __align__(128) char smem[];
    __shared__ __align__(8) uint64_t barr[9];
    __shared__ __align__(16) float sbias[BN];

    const int tid  = threadIdx.x;
    const int lane = tid & 31;
    const int warp = tid >> 5;
    const int wm   = warp >> 2;
    const int wn   = warp & 3;
    const int bm   = blockIdx.y * BM;
    const uint32_t sbase = smem_u32(smem);
    const uint32_t fb0   = smem_u32(barr);
    const int n0g = blockIdx.x * 64;

    if (tid == 0) {
        #pragma unroll
        for (int i = 0; i < NSTAGE; ++i) {
            mbar_init(fb0 + i * 8, 1);        // full (tx)
            mbar_init(fb0 + 32 + i * 8, 16);  // empty (16 consumer warps)
        }
        mbar_init(fb0 + 64, 16);              // epilogue-done
        FENCE_ASYNC();
    }
    if (tid < BN) sbias[tid] = g_bias[blockIdx.x * BN + tid];
    __syncthreads();

    if (warp < 16) {
        // ================= CONSUMERS: free-running =================
        float acc[2][8][4];
        #pragma unroll
        for (int a = 0; a < 2; ++a)
            #pragma unroll
            for (int b = 0; b < 8; ++b)
                #pragma unroll
                for (int v = 0; v < 4; ++v) acc[a][b][v] = 0.0f;
        float c_reg[16];
        #pragma unroll
        for (int i = 0; i < 16; ++i) c_reg[i] = 0.0f;

        unsigned ck = 0;
        const int odd = lane & 1;
        const int rb  = wm * 32 + (lane >> 2) + (odd ? 8 : 0);

        for (int s = 0; s < SLEN; ++s) {
            const int NS = (s == 0) ? NSK : 2 * NSK;
            for (int j = 0; j < NS; ++j) {
                const int st = ck & 3;
                mbar_wait(fb0 + st * 8, (ck >> 2) & 1);
                slab_mma(sbase + st * STAGE_B, wm, wn, lane, acc);
                if (lane == 0) mbar_arrive(fb0 + 32 + st * 8);
                ++ck;
            }
            // fused cell update -> hstg[s&1]
            char* hstg = smem + HSTG_OFF + (s & 1) * A_TILE_B;
            const bool last = (s == SLEN - 1);
            #pragma unroll
            for (int mt = 0; mt < 2; ++mt) {
                #pragma unroll
                for (int nt = 0; nt < 8; ++nt) {
                    float v0 = acc[mt][nt][0], v1 = acc[mt][nt][1];
                    float v2 = acc[mt][nt][2], v3 = acc[mt][nt][3];
                    const float s0 = __shfl_xor_sync(0xffffffffu, v0, 1);
                    const float s1 = __shfl_xor_sync(0xffffffffu, v1, 1);
                    const float s2 = __shfl_xor_sync(0xffffffffu, v2, 1);
                    const float s3 = __shfl_xor_sync(0xffffffffu, v3, 1);
                    const int row = rb + mt * 16;
                    const int u   = wn * 16 + nt * 2 + ((lane & 3) >> 1);
                    float xi = odd ? s2 : v0;
                    float xf = odd ? s3 : v1;
                    float xg = odd ? v2 : s0;
                    float xo = odd ? v3 : s1;
                    const float4 bv = *reinterpret_cast<const float4*>(&sbias[4 * u]);
                    xi += bv.x; xf += bv.y; xg += bv.z; xo += bv.w;
                    const float ig = sigm(xi), fg = sigm(xf);
                    const float gg = tanh_f(xg), og = sigm(xo);
                    const float cc = fg * c_reg[mt * 8 + nt] + ig * gg;
                    c_reg[mt * 8 + nt] = cc;
                    const float hh = og * tanh_f(cc);
                    *reinterpret_cast<__half*>(hstg + sw(row, u >> 3) + (u & 7) * 2)
                        = __float2half_rn(hh);
                    if (last) {
                        const size_t gi = (size_t)(bm + row) * HID + n0g + u;
                        h_g[gi] = hh;
                        c_g[gi] = cc;
                    }
                    acc[mt][nt][0] = 0.0f; acc[mt][nt][1] = 0.0f;
                    acc[mt][nt][2] = 0.0f; acc[mt][nt][3] = 0.0f;
                }
            }
            __syncwarp();
            if (lane == 0) mbar_arrive(fb0 + 64);   // epilogue(s) done
        }
    } else if (tid == 512) {
        // ================= PRODUCER =================
        int is = 0, ij = 0, bar_seen = 0;
        unsigned pk = 0;

        // prologue: first 4 x-slabs of step 0
        #pragma unroll
        for (int i = 0; i < NSTAGE; ++i) {
            expect_tx(fb0 + i * 8, STAGE_B);
            bulk_ld(sbase + i * STAGE_B,
                    g_XT + ((size_t)(blockIdx.y * SLEN) * NSK + i) * A_TILE_H,
                    A_TILE_B, fb0 + i * 8);
            bulk_ld(sbase + i * STAGE_B + A_TILE_B,
                    g_WxT + (size_t)blockIdx.x * NT_H + (size_t)i * B_TILE_H,
                    B_TILE_B, fb0 + i * 8);
        }
        ij = NSTAGE;

        for (int s = 0; s < SLEN; ++s) {
            const int NS = (s == 0) ? NSK : 2 * NSK;
            for (int j = 0; j < NS; ++j) {
                const int st = pk & 3;
                mbar_wait(fb0 + 32 + st * 8, (pk >> 2) & 1);
                if (is < SLEN) {
                    const __half *aT, *bT;
                    if (ij < NSK) {
                        aT = g_XT + ((size_t)(blockIdx.y * SLEN + is) * NSK + ij) * A_TILE_H;
                        bT = g_WxT + (size_t)blockIdx.x * NT_H + (size_t)ij * B_TILE_H;
                    } else {
                        if (bar_seen < is) {
                            const unsigned target = (unsigned)is * NCTA;
                            unsigned v;
                            do {
                                asm volatile("ld.acquire.gpu.global.u32 %0, [%1];"
                                             : "=r"(v) : "l"(&g_cnt) : "memory");
                            } while (v < target);
                            FENCE_ASYNC();
                            bar_seen = is;
                        }
                        aT = g_HaT[is & 1] + (size_t)blockIdx.y * MT_H
                           + (size_t)(ij - NSK) * A_TILE_H;
                        bT = g_WhT + (size_t)blockIdx.x * NT_H + (size_t)(ij - NSK) * B_TILE_H;
                    }
                    expect_tx(fb0 + st * 8, STAGE_B);
                    bulk_ld(sbase + st * STAGE_B,            aT, A_TILE_B, fb0 + st * 8);
                    bulk_ld(sbase + st * STAGE_B + A_TILE_B, bT, B_TILE_B, fb0 + st * 8);
                    if (++ij == ((is == 0) ? NSK : 2 * NSK)) { ij = 0; ++is; }
                }
                ++pk;
            }
            // step boundary: wait epilogue(s), store h tile, arrive grid barrier
            if (s + 1 < SLEN) {
                mbar_wait(fb0 + 64, s & 1);
                FENCE_ASYNC();
                bulk_st(g_HaT[(s + 1) & 1] + (size_t)blockIdx.y * MT_H
                            + (size_t)blockIdx.x * A_TILE_H,
                        sbase + HSTG_OFF + (s & 1) * A_TILE_B, A_TILE_B);
                asm volatile("cp.async.bulk.commit_group;" ::: "memory");
                asm volatile("cp.async.bulk.wait_group 0;" ::: "memory");
                __threadfence();
                atomicAdd(&g_cnt, 1u);
            }
        }
    }
}

// ---------------------------------------------------------------------------
extern "C" void kernel_launch(void* const* d_in, const int* in_sizes, int n_in,
                              void* d_out, int out_size)
{
    const float* x = nullptr;
    const float* w[8] = {nullptr};
    const float* b[8] = {nullptr};
    int wi = 0, bi = 0;
    for (int i = 0; i < n_in; ++i) {
        const int sz = in_sizes[i];
        if (sz == HID * HID)      { if (wi < 8) w[wi++] = (const float*)d_in[i]; }
        else if (sz == HID)       { if (bi < 8) b[bi++] = (const float*)d_in[i]; }
        else                      { x = (const float*)d_in[i]; }
    }

    float* h = (float*)d_out;
    float* c = h + (size_t)HID * HID;

    cudaFuncSetAttribute(lstm_persistent, cudaFuncAttributeMaxDynamicSharedMemorySize, SMEM_P);

    prep_weights<<<(NGC * 128 + 255) / 256, 256>>>(
        w[0], w[1], w[2], w[3], w[4], w[5], w[6], w[7]);
    {
        const size_t total = (size_t)HID * SLEN * 128;
        prep_x<<<(unsigned)((total + 255) / 256), 256>>>(x);
    }
    prep_state<<<(HID * HID) / 256, 256>>>(
        b[0], b[1], b[2], b[3], b[4], b[5], b[6], b[7]);

    dim3 grid(NGC / BN, HID / BM);            // 16 x 8 = 128 CTAs, 1 per SM
    lstm_persistent<<<grid, 544, SMEM_P>>>(h, c);
}